// round 10
// baseline (speedup 1.0000x reference)
#include <cuda_runtime.h>
#include <cstdint>
#include <cstddef>

#define TSTEPS 500
#define BATCH  128

__device__ float g_X1[64000 * 256];
__device__ float g_X2[64000 * 128];
__device__ float g_GIA[64000 * 768];
__device__ float g_encT[128 * 256 * 256];
__device__ float g_ALN[64000 * 256];
__device__ float g_HA[2][128 * 256];
__device__ float g_H1[128 * 256];
__device__ float g_H2[128 * 256];
__device__ float g_GH1[128 * 768];
__device__ float g_GH2[128 * 768];
__device__ float g_CTX[128 * 256];
__device__ float g_DEC[128 * 256];
__device__ float g_Y1[128 * 256];
__device__ float g_Y2[128 * 256];
__device__ unsigned g_cnt;
__device__ volatile unsigned g_gen;

template <bool RELU>
__global__ __launch_bounds__(256) void gemm_k(const float* __restrict__ A,
                                              const float* __restrict__ W,
                                              const float* __restrict__ bias,
                                              float* __restrict__ C, int K, int N) {
    __shared__ float As[16 * 68];
    __shared__ float Ws[16 * 68];
    const int m0 = blockIdx.x * 64, n0 = blockIdx.y * 64;
    const int tid = threadIdx.x, tx = tid & 15, ty = tid >> 4;
    float acc[4][4] = {};
    for (int k0 = 0; k0 < K; k0 += 16) {
        int idx = tid;
#pragma unroll
        for (int it = 0; it < 4; it++) {
            int m = idx >> 4, k = idx & 15;
            As[k * 68 + m] = A[(size_t)(m0 + m) * K + k0 + k];
            Ws[k * 68 + m] = W[(size_t)(n0 + m) * K + k0 + k];
            idx += 256;
        }
        __syncthreads();
#pragma unroll
        for (int k = 0; k < 16; k++) {
            float4 a = *(const float4*)&As[k * 68 + ty * 4];
            float4 w = *(const float4*)&Ws[k * 68 + tx * 4];
            acc[0][0] += a.x * w.x; acc[0][1] += a.x * w.y; acc[0][2] += a.x * w.z; acc[0][3] += a.x * w.w;
            acc[1][0] += a.y * w.x; acc[1][1] += a.y * w.y; acc[1][2] += a.y * w.z; acc[1][3] += a.y * w.w;
            acc[2][0] += a.z * w.x; acc[2][1] += a.z * w.y; acc[2][2] += a.z * w.z; acc[2][3] += a.z * w.w;
            acc[3][0] += a.w * w.x; acc[3][1] += a.w * w.y; acc[3][2] += a.w * w.z; acc[3][3] += a.w * w.w;
        }
        __syncthreads();
    }
#pragma unroll
    for (int i = 0; i < 4; i++) {
        int m = m0 + ty * 4 + i;
#pragma unroll
        for (int j = 0; j < 4; j++) {
            float v = acc[i][j] + bias[n0 + tx * 4 + j];
            if (RELU) v = fmaxf(v, 0.f);
            C[(size_t)m * N + n0 + tx * 4 + j] = v;
        }
    }
}

__global__ void transpose_enc_k(const float* __restrict__ enc) {
    __shared__ float tile[32][33];
    const int b = blockIdx.x, l0 = blockIdx.y * 32, d0 = blockIdx.z * 32;
    const int j = threadIdx.x & 31, i0 = threadIdx.x >> 5;
    const float* base = enc + (size_t)b * 65536;
#pragma unroll
    for (int ii = 0; ii < 32; ii += 8)
        tile[i0 + ii][j] = base[(size_t)(l0 + i0 + ii) * 256 + d0 + j];
    __syncthreads();
    float* ob = g_encT + (size_t)b * 65536;
#pragma unroll
    for (int ii = 0; ii < 32; ii += 8)
        ob[(size_t)(d0 + i0 + ii) * 256 + l0 + j] = tile[j][i0 + ii];
}

__global__ void transpose_aln_k(float* __restrict__ out) {
    __shared__ float tile[32][33];
    const int b = blockIdx.x, l0 = blockIdx.y * 32, t0 = blockIdx.z * 32;
    const int j = threadIdx.x & 31, i0 = threadIdx.x >> 5;
#pragma unroll
    for (int ii = 0; ii < 32; ii += 8) {
        int t = t0 + i0 + ii;
        if (t < TSTEPS) tile[i0 + ii][j] = g_ALN[((size_t)t * BATCH + b) * 256 + l0 + j];
    }
    __syncthreads();
#pragma unroll
    for (int ii = 0; ii < 32; ii += 8) {
        int t = t0 + j, l = l0 + i0 + ii;
        if (t < TSTEPS) out[((size_t)b * 256 + l) * TSTEPS + t] = tile[j][i0 + ii];
    }
}

__device__ __forceinline__ float sigm(float x) { return 1.f / (1.f + expf(-x)); }

__device__ __forceinline__ void gridbar(unsigned& lgen) {
    __syncthreads();
    lgen++;
    if (threadIdx.x == 0) {
        __threadfence();
        unsigned old = atomicAdd(&g_cnt, 1u);
        if (old == gridDim.x - 1) {
            g_cnt = 0;
            __threadfence();
            g_gen = lgen;
        } else {
            while ((int)(g_gen - lgen) < 0) { }
            __threadfence();
        }
    }
    __syncthreads();
}

__device__ __forceinline__ void load_A32(const float* __restrict__ src, int b0, float* As) {
    for (int idx = threadIdx.x; idx < 32 * 256; idx += 256) {
        int r = idx >> 8, c = idx & 255;
        As[r * 260 + c] = src[(size_t)(b0 + r) * 256 + c];
    }
}

__device__ __forceinline__ void load_W24(const float* __restrict__ w, int c0, float* Ws) {
    for (int idx = threadIdx.x; idx < 24 * 256; idx += 256) {
        int row = idx >> 8, k = idx & 255;
        int g = row >> 3, i = row & 7;
        Ws[row * 260 + k] = w[(size_t)(g * 256 + c0 + i) * 256 + k];
    }
}

__device__ __forceinline__ void gate_gemm(const float* As, const float* Ws,
                                          int r, int cg, float acc[3]) {
    const float4* a4 = (const float4*)(As + r * 260);
    const float4* w0 = (const float4*)(Ws + cg * 260);
    const float4* w1 = (const float4*)(Ws + (8 + cg) * 260);
    const float4* w2 = (const float4*)(Ws + (16 + cg) * 260);
#pragma unroll 8
    for (int k = 0; k < 64; k++) {
        float4 a = a4[k];
        float4 b0 = w0[k], b1 = w1[k], b2 = w2[k];
        acc[0] += (a.x * b0.x + a.y * b0.y) + (a.z * b0.z + a.w * b0.w);
        acc[1] += (a.x * b1.x + a.y * b1.y) + (a.z * b1.z + a.w * b1.w);
        acc[2] += (a.x * b2.x + a.y * b2.y) + (a.z * b2.z + a.w * b2.w);
    }
}

__device__ void phase_gh(const float* __restrict__ H, const float* __restrict__ whh,
                         const float* __restrict__ bhh, float* __restrict__ gh, float* sm) {
    const int b0 = (blockIdx.x >> 5) * 32, c0 = (blockIdx.x & 31) * 8;
    float* As = sm;
    float* Ws = sm + 32 * 260;
    load_A32(H, b0, As);
    load_W24(whh, c0, Ws);
    __syncthreads();
    const int r = threadIdx.x >> 3, cg = threadIdx.x & 7, c = c0 + cg;
    float acc[3] = { bhh[c], bhh[256 + c], bhh[512 + c] };
    gate_gemm(As, Ws, r, cg, acc);
    const size_t b = b0 + r;
    gh[b * 768 + c] = acc[0];
    gh[b * 768 + 256 + c] = acc[1];
    gh[b * 768 + 512 + c] = acc[2];
    __syncthreads();
}

__device__ void phase_attn0(const float* __restrict__ Hp, const float* __restrict__ whh,
                            const float* __restrict__ bhh, int t,
                            float* __restrict__ Hn, float* sm) {
    const int b0 = (blockIdx.x >> 5) * 32, c0 = (blockIdx.x & 31) * 8;
    float* As = sm;
    float* Ws = sm + 32 * 260;
    load_A32(Hp, b0, As);
    load_W24(whh, c0, Ws);
    __syncthreads();
    const int r = threadIdx.x >> 3, cg = threadIdx.x & 7, c = c0 + cg;
    float acc[3] = { bhh[c], bhh[256 + c], bhh[512 + c] };
    gate_gemm(As, Ws, r, cg, acc);
    const int b = b0 + r;
    const float* gb = g_GIA + ((size_t)b * TSTEPS + t) * 768;  // rows are (b,t)-ordered
    float rr = sigm(gb[c] + acc[0]);
    float zz = sigm(gb[256 + c] + acc[1]);
    float nn = tanhf(gb[512 + c] + rr * acc[2]);
    float hp = As[r * 260 + c];
    Hn[(size_t)b * 256 + c] = (1.f - zz) * nn + zz * hp;
    __syncthreads();
}

__device__ void phase_gru(const float* __restrict__ X, const float* __restrict__ wih,
                          const float* __restrict__ bih, const float* __restrict__ gh,
                          float* __restrict__ h, float* __restrict__ y, float* sm) {
    const int b0 = (blockIdx.x >> 5) * 32, c0 = (blockIdx.x & 31) * 8;
    float* As = sm;
    float* Ws = sm + 32 * 260;
    load_A32(X, b0, As);
    load_W24(wih, c0, Ws);
    __syncthreads();
    const int r = threadIdx.x >> 3, cg = threadIdx.x & 7, c = c0 + cg;
    float acc[3] = { bih[c], bih[256 + c], bih[512 + c] };
    gate_gemm(As, Ws, r, cg, acc);
    const int b = b0 + r;
    const float* gb = gh + (size_t)b * 768;
    float rr = sigm(acc[0] + gb[c]);
    float zz = sigm(acc[1] + gb[256 + c]);
    float nn = tanhf(acc[2] + rr * gb[512 + c]);
    float hp = h[(size_t)b * 256 + c];
    float hn = (1.f - zz) * nn + zz * hp;
    h[(size_t)b * 256 + c] = hn;
    y[(size_t)b * 256 + c] = As[r * 260 + c] + hn;
    __syncthreads();
}

__device__ void phase_proj2(const float* __restrict__ Y, const float* __restrict__ w,
                            const float* __restrict__ bias, float* __restrict__ out,
                            int tprev, float* sm) {
    const int b0 = (blockIdx.x >> 5) * 32, c0 = (blockIdx.x & 31) * 5;
    float* As = sm;
    float* Ws = sm + 32 * 260;
    load_A32(Y, b0, As);
    for (int idx = threadIdx.x; idx < 5 * 256; idx += 256) {
        int row = idx >> 8, k = idx & 255;
        Ws[row * 260 + k] = w[(size_t)(c0 + row) * 256 + k];
    }
    __syncthreads();
    const int r = threadIdx.x >> 3, j = threadIdx.x & 7;
    if (j < 5) {
        float a0 = 0.f, a1 = 0.f;
        const float4* a4 = (const float4*)(As + r * 260);
        const float4* w4 = (const float4*)(Ws + j * 260);
#pragma unroll 8
        for (int k = 0; k < 64; k++) {
            float4 a = a4[k], b = w4[k];
            a0 += a.x * b.x + a.y * b.y;
            a1 += a.z * b.z + a.w * b.w;
        }
        int b = b0 + r;
        out[(size_t)b * 80000 + (size_t)tprev * 160 + c0 + j] = a0 + a1 + bias[c0 + j];
    }
    __syncthreads();
}

__device__ void phase_proj1(const float* __restrict__ Hn, const float* __restrict__ w,
                            const float* __restrict__ bias, float* sm) {
    const int b0 = (blockIdx.x >> 5) * 32, n0 = (blockIdx.x & 31) * 8;
    float* As = sm;             // [32][516]
    float* Ws = sm + 32 * 516;  // [8][516]
    for (int idx = threadIdx.x; idx < 32 * 512; idx += 256) {
        int r = idx >> 9, k = idx & 511;
        As[r * 516 + k] = (k < 256) ? g_CTX[(size_t)(b0 + r) * 256 + k]
                                    : Hn[(size_t)(b0 + r) * 256 + (k - 256)];
    }
    for (int idx = threadIdx.x; idx < 8 * 512; idx += 256) {
        int j = idx >> 9, k = idx & 511;
        Ws[j * 516 + k] = w[(size_t)(n0 + j) * 512 + k];
    }
    __syncthreads();
    const int r = threadIdx.x >> 3, j = threadIdx.x & 7;
    float a0 = 0.f, a1 = 0.f;
    const float4* a4 = (const float4*)(As + r * 516);
    const float4* w4 = (const float4*)(Ws + j * 516);
#pragma unroll 8
    for (int k = 0; k < 128; k++) {
        float4 a = a4[k], b = w4[k];
        a0 += a.x * b.x + a.y * b.y;
        a1 += a.z * b.z + a.w * b.w;
    }
    g_DEC[(size_t)(b0 + r) * 256 + n0 + j] = a0 + a1 + bias[n0 + j];
    __syncthreads();
}

__device__ void phase_attn_soft(const float* __restrict__ enc, const float* __restrict__ Hn,
                                int t, float* sm) {
    __shared__ float red[8];
    __shared__ float redv[2];
    const int b = blockIdx.x, tid = threadIdx.x;
    float* q = sm;
    float* sc = sm + 256;
    q[tid] = Hn[(size_t)b * 256 + tid];
    __syncthreads();
    const float* ep = g_encT + (size_t)b * 65536 + tid;
    float s0 = 0.f, s1 = 0.f, s2 = 0.f, s3 = 0.f;
#pragma unroll 4
    for (int d = 0; d < 256; d += 4) {
        s0 += q[d] * ep[d * 256];
        s1 += q[d + 1] * ep[(d + 1) * 256];
        s2 += q[d + 2] * ep[(d + 2) * 256];
        s3 += q[d + 3] * ep[(d + 3) * 256];
    }
    float s = (s0 + s1) + (s2 + s3);
    float m = s;
#pragma unroll
    for (int off = 16; off > 0; off >>= 1) m = fmaxf(m, __shfl_xor_sync(0xffffffffu, m, off));
    const int w = tid >> 5;
    if ((tid & 31) == 0) red[w] = m;
    __syncthreads();
    if (tid < 8) {
        float x = red[tid];
#pragma unroll
        for (int off = 4; off > 0; off >>= 1) x = fmaxf(x, __shfl_xor_sync(0xffu, x, off));
        if (tid == 0) redv[0] = x;
    }
    __syncthreads();
    float e = expf(s - redv[0]);
    float su = e;
#pragma unroll
    for (int off = 16; off > 0; off >>= 1) su += __shfl_xor_sync(0xffffffffu, su, off);
    if ((tid & 31) == 0) red[w] = su;
    __syncthreads();
    if (tid < 8) {
        float x = red[tid];
#pragma unroll
        for (int off = 4; off > 0; off >>= 1) x += __shfl_xor_sync(0xffu, x, off);
        if (tid == 0) redv[1] = x;
    }
    __syncthreads();
    float wgt = e / redv[1];
    sc[tid] = wgt;
    g_ALN[((size_t)t * BATCH + b) * 256 + tid] = wgt;
    __syncthreads();
    const float* ep2 = enc + (size_t)b * 65536 + tid;
    float c0 = 0.f, c1 = 0.f, c2 = 0.f, c3 = 0.f;
#pragma unroll 4
    for (int l = 0; l < 256; l += 4) {
        c0 += sc[l] * ep2[l * 256];
        c1 += sc[l + 1] * ep2[(l + 1) * 256];
        c2 += sc[l + 2] * ep2[(l + 2) * 256];
        c3 += sc[l + 3] * ep2[(l + 3) * 256];
    }
    g_CTX[(size_t)b * 256 + tid] = (c0 + c1) + (c2 + c3);
    __syncthreads();
}

__global__ __launch_bounds__(256) void decoder_loop(
    const float* __restrict__ enc,
    const float* __restrict__ attn_whh, const float* __restrict__ attn_bhh,
    const float* __restrict__ proj1_w, const float* __restrict__ proj1_b,
    const float* __restrict__ rnn1_wih, const float* __restrict__ rnn1_whh,
    const float* __restrict__ rnn1_bih, const float* __restrict__ rnn1_bhh,
    const float* __restrict__ rnn2_wih, const float* __restrict__ rnn2_whh,
    const float* __restrict__ rnn2_bih, const float* __restrict__ rnn2_bhh,
    const float* __restrict__ proj2_w, const float* __restrict__ proj2_b,
    float* __restrict__ out_mel) {
    extern __shared__ float sm[];
    unsigned lgen = g_gen;
    {
        int i = blockIdx.x * 256 + threadIdx.x;
        g_HA[0][i] = 0.f;
        g_H1[i] = 0.f;
        g_H2[i] = 0.f;
    }
    gridbar(lgen);
    for (int t = 0; t < TSTEPS; t++) {
        const int p = t & 1;
        phase_attn0(g_HA[p], attn_whh, attn_bhh, t, g_HA[p ^ 1], sm);
        phase_gh(g_H1, rnn1_whh, rnn1_bhh, g_GH1, sm);
        phase_gh(g_H2, rnn2_whh, rnn2_bhh, g_GH2, sm);
        if (t > 0) phase_proj2(g_Y2, proj2_w, proj2_b, out_mel, t - 1, sm);
        gridbar(lgen);
        phase_attn_soft(enc, g_HA[p ^ 1], t, sm);
        gridbar(lgen);
        phase_proj1(g_HA[p ^ 1], proj1_w, proj1_b, sm);
        gridbar(lgen);
        phase_gru(g_DEC, rnn1_wih, rnn1_bih, g_GH1, g_H1, g_Y1, sm);
        gridbar(lgen);
        phase_gru(g_Y1, rnn2_wih, rnn2_bih, g_GH2, g_H2, g_Y2, sm);
        gridbar(lgen);
    }
    phase_proj2(g_Y2, proj2_w, proj2_b, out_mel, TSTEPS - 1, sm);
}

extern "C" void kernel_launch(void* const* d_in, const int* in_sizes, int n_in,
                              void* d_out, int out_size) {
    const float* dec      = (const float*)d_in[0];
    const float* enc      = (const float*)d_in[1];
    const float* pre_w1   = (const float*)d_in[2];
    const float* pre_b1   = (const float*)d_in[3];
    const float* pre_w2   = (const float*)d_in[4];
    const float* pre_b2   = (const float*)d_in[5];
    const float* attn_wih = (const float*)d_in[6];
    const float* attn_whh = (const float*)d_in[7];
    const float* attn_bih = (const float*)d_in[8];
    const float* attn_bhh = (const float*)d_in[9];
    const float* proj1_w  = (const float*)d_in[10];
    const float* proj1_b  = (const float*)d_in[11];
    const float* rnn1_wih = (const float*)d_in[12];
    const float* rnn1_whh = (const float*)d_in[13];
    const float* rnn1_bih = (const float*)d_in[14];
    const float* rnn1_bhh = (const float*)d_in[15];
    const float* rnn2_wih = (const float*)d_in[16];
    const float* rnn2_whh = (const float*)d_in[17];
    const float* rnn2_bih = (const float*)d_in[18];
    const float* rnn2_bhh = (const float*)d_in[19];
    const float* proj2_w  = (const float*)d_in[20];
    const float* proj2_b  = (const float*)d_in[21];
    float* out = (float*)d_out;

    float *x1, *x2, *gia;
    cudaGetSymbolAddress((void**)&x1, g_X1);
    cudaGetSymbolAddress((void**)&x2, g_X2);
    cudaGetSymbolAddress((void**)&gia, g_GIA);

    const int SMEM = 40 * 516 * 4;  // 82,560 B (proj1 phase is the max user)
    cudaFuncSetAttribute(decoder_loop, cudaFuncAttributeMaxDynamicSharedMemorySize, SMEM);

    transpose_enc_k<<<dim3(128, 8, 8), 256>>>(enc);
    gemm_k<true><<<dim3(1000, 4), 256>>>(dec, pre_w1, pre_b1, x1, 80, 256);
    gemm_k<true><<<dim3(1000, 2), 256>>>(x1, pre_w2, pre_b2, x2, 256, 128);
    gemm_k<false><<<dim3(1000, 12), 256>>>(x2, attn_wih, attn_bih, gia, 128, 768);
    decoder_loop<<<128, 256, SMEM>>>(enc, attn_whh, attn_bhh, proj1_w, proj1_b,
                                     rnn1_wih, rnn1_whh, rnn1_bih, rnn1_bhh,
                                     rnn2_wih, rnn2_whh, rnn2_bih, rnn2_bhh,
                                     proj2_w, proj2_b, out);
    transpose_aln_k<<<dim3(128, 8, 16), 256>>>(out + 10240000);
}

// round 11
// speedup vs baseline: 1.5044x; 1.5044x over previous
#include <cuda_runtime.h>
#include <cstdint>
#include <cstddef>

#define TSTEPS 500
#define BATCH  128

// smem float offsets
#define OWA  0
#define OW1I 6240
#define OW1H 12480
#define OW2I 18720
#define OW2H 24960
#define OP1  31200
#define OP2  35328
#define OST  36628
#define SMEMF 53140   /* 212,560 bytes */

__device__ float g_X1[64000 * 256];
__device__ float g_X2[64000 * 128];
__device__ float g_GIA[64000 * 768];
__device__ float g_encT[128 * 256 * 256];
__device__ float g_ALN[64000 * 256];
__device__ float g_HA[2][128 * 256];
__device__ float g_H1[128 * 256];
__device__ float g_H2[128 * 256];
__device__ float g_CTX[128 * 256];
__device__ float g_DEC[128 * 256];
__device__ float g_Y1[128 * 256];
__device__ float g_Y2[128 * 256];
__device__ unsigned g_cnt;
__device__ volatile unsigned g_gen;

typedef unsigned long long ull;

__device__ __forceinline__ ull ffma2(ull a, ull b, ull c) {
    ull d;
    asm("fma.rn.f32x2 %0, %1, %2, %3;" : "=l"(d) : "l"(a), "l"(b), "l"(c));
    return d;
}
__device__ __forceinline__ float unpack_sum(ull v) {
    float2 f = *(float2*)&v;
    return f.x + f.y;
}

template <bool RELU>
__global__ __launch_bounds__(256) void gemm_k(const float* __restrict__ A,
                                              const float* __restrict__ W,
                                              const float* __restrict__ bias,
                                              float* __restrict__ C, int K, int N) {
    __shared__ float As[16 * 68];
    __shared__ float Ws[16 * 68];
    const int m0 = blockIdx.x * 64, n0 = blockIdx.y * 64;
    const int tid = threadIdx.x, tx = tid & 15, ty = tid >> 4;
    float acc[4][4] = {};
    for (int k0 = 0; k0 < K; k0 += 16) {
        int idx = tid;
#pragma unroll
        for (int it = 0; it < 4; it++) {
            int m = idx >> 4, k = idx & 15;
            As[k * 68 + m] = A[(size_t)(m0 + m) * K + k0 + k];
            Ws[k * 68 + m] = W[(size_t)(n0 + m) * K + k0 + k];
            idx += 256;
        }
        __syncthreads();
#pragma unroll
        for (int k = 0; k < 16; k++) {
            float4 a = *(const float4*)&As[k * 68 + ty * 4];
            float4 w = *(const float4*)&Ws[k * 68 + tx * 4];
            acc[0][0] += a.x * w.x; acc[0][1] += a.x * w.y; acc[0][2] += a.x * w.z; acc[0][3] += a.x * w.w;
            acc[1][0] += a.y * w.x; acc[1][1] += a.y * w.y; acc[1][2] += a.y * w.z; acc[1][3] += a.y * w.w;
            acc[2][0] += a.z * w.x; acc[2][1] += a.z * w.y; acc[2][2] += a.z * w.z; acc[2][3] += a.z * w.w;
            acc[3][0] += a.w * w.x; acc[3][1] += a.w * w.y; acc[3][2] += a.w * w.z; acc[3][3] += a.w * w.w;
        }
        __syncthreads();
    }
#pragma unroll
    for (int i = 0; i < 4; i++) {
        int m = m0 + ty * 4 + i;
#pragma unroll
        for (int j = 0; j < 4; j++) {
            float v = acc[i][j] + bias[n0 + tx * 4 + j];
            if (RELU) v = fmaxf(v, 0.f);
            C[(size_t)m * N + n0 + tx * 4 + j] = v;
        }
    }
}

__global__ void transpose_enc_k(const float* __restrict__ enc) {
    __shared__ float tile[32][33];
    const int b = blockIdx.x, l0 = blockIdx.y * 32, d0 = blockIdx.z * 32;
    const int j = threadIdx.x & 31, i0 = threadIdx.x >> 5;
    const float* base = enc + (size_t)b * 65536;
#pragma unroll
    for (int ii = 0; ii < 32; ii += 8)
        tile[i0 + ii][j] = base[(size_t)(l0 + i0 + ii) * 256 + d0 + j];
    __syncthreads();
    float* ob = g_encT + (size_t)b * 65536;
#pragma unroll
    for (int ii = 0; ii < 32; ii += 8)
        ob[(size_t)(d0 + i0 + ii) * 256 + l0 + j] = tile[j][i0 + ii];
}

__global__ void transpose_aln_k(float* __restrict__ out) {
    __shared__ float tile[32][33];
    const int b = blockIdx.x, l0 = blockIdx.y * 32, t0 = blockIdx.z * 32;
    const int j = threadIdx.x & 31, i0 = threadIdx.x >> 5;
#pragma unroll
    for (int ii = 0; ii < 32; ii += 8) {
        int t = t0 + i0 + ii;
        if (t < TSTEPS) tile[i0 + ii][j] = g_ALN[((size_t)t * BATCH + b) * 256 + l0 + j];
    }
    __syncthreads();
#pragma unroll
    for (int ii = 0; ii < 32; ii += 8) {
        int t = t0 + j, l = l0 + i0 + ii;
        if (t < TSTEPS) out[((size_t)b * 256 + l) * TSTEPS + t] = tile[j][i0 + ii];
    }
}

__device__ __forceinline__ float sigm(float x) { return 1.f / (1.f + expf(-x)); }

__device__ __forceinline__ void gridbar(unsigned& lgen) {
    __syncthreads();
    lgen++;
    if (threadIdx.x == 0) {
        __threadfence();
        if (atomicAdd(&g_cnt, 1u) == gridDim.x - 1) {
            g_cnt = 0;
            __threadfence();
            g_gen = lgen;
        } else {
            while ((int)(g_gen - lgen) < 0) __nanosleep(64);
            __threadfence();
        }
    }
    __syncthreads();
}

__device__ __forceinline__ void load_A32(const float* __restrict__ src, int b0, float* As) {
    for (int idx = threadIdx.x; idx < 32 * 64; idx += 256) {
        int r = idx >> 6, q = idx & 63;
        *(float4*)(As + r * 260 + q * 4) = *(const float4*)(src + (size_t)(b0 + r) * 256 + q * 4);
    }
}

// preload a [768][256] gate matrix's column slice (3 gates x 8 cols) into smem [24][260]
__device__ __forceinline__ void preload_W24(const float* __restrict__ w, int c0, float* Wd) {
    for (int idx = threadIdx.x; idx < 24 * 64; idx += 256) {
        int row = idx >> 6, q = idx & 63;
        int g = row >> 3, i = row & 7;
        *(float4*)(Wd + row * 260 + q * 4) =
            *(const float4*)(w + (size_t)(g * 256 + c0 + i) * 256 + q * 4);
    }
}

// gate dot products using packed f32x2 FMA
__device__ __forceinline__ void gate3(const float* As, const float* Ws, int r, int cg, float out[3]) {
    const ulonglong2* a8 = (const ulonglong2*)(As + r * 260);
    const ulonglong2* w0 = (const ulonglong2*)(Ws + cg * 260);
    const ulonglong2* w1 = (const ulonglong2*)(Ws + (8 + cg) * 260);
    const ulonglong2* w2 = (const ulonglong2*)(Ws + (16 + cg) * 260);
    ull acc0 = 0, acc1 = 0, acc2 = 0;
#pragma unroll 8
    for (int k = 0; k < 64; k++) {
        ulonglong2 a = a8[k];
        ulonglong2 b0 = w0[k], b1 = w1[k], b2 = w2[k];
        acc0 = ffma2(a.x, b0.x, acc0); acc0 = ffma2(a.y, b0.y, acc0);
        acc1 = ffma2(a.x, b1.x, acc1); acc1 = ffma2(a.y, b1.y, acc1);
        acc2 = ffma2(a.x, b2.x, acc2); acc2 = ffma2(a.y, b2.y, acc2);
    }
    out[0] = unpack_sum(acc0);
    out[1] = unpack_sum(acc1);
    out[2] = unpack_sum(acc2);
}

__global__ __launch_bounds__(256) void decoder_loop(
    const float* __restrict__ enc,
    const float* __restrict__ attn_whh, const float* __restrict__ attn_bhh,
    const float* __restrict__ proj1_w, const float* __restrict__ proj1_b,
    const float* __restrict__ rnn1_wih, const float* __restrict__ rnn1_whh,
    const float* __restrict__ rnn1_bih, const float* __restrict__ rnn1_bhh,
    const float* __restrict__ rnn2_wih, const float* __restrict__ rnn2_whh,
    const float* __restrict__ rnn2_bih, const float* __restrict__ rnn2_bhh,
    const float* __restrict__ proj2_w, const float* __restrict__ proj2_b,
    float* __restrict__ out_mel) {
    extern __shared__ float sm[];
    unsigned lgen = g_gen;
    const int tid = threadIdx.x;
    const int bb = blockIdx.x >> 5, cj = blockIdx.x & 31;
    const int b0 = bb * 32, c0 = cj * 8;
    const int r = tid >> 3, cg = tid & 7, c = c0 + cg;
    float* As = sm + OST;

    // ---- one-time: preload all weight slices into resident smem ----
    preload_W24(attn_whh, c0, sm + OWA);
    preload_W24(rnn1_wih, c0, sm + OW1I);
    preload_W24(rnn1_whh, c0, sm + OW1H);
    preload_W24(rnn2_wih, c0, sm + OW2I);
    preload_W24(rnn2_whh, c0, sm + OW2H);
    {
        const int n0 = cj * 8;
        for (int idx = tid; idx < 8 * 128; idx += 256) {
            int row = idx >> 7, q = idx & 127;
            *(float4*)(sm + OP1 + row * 516 + q * 4) =
                *(const float4*)(proj1_w + (size_t)(n0 + row) * 512 + q * 4);
        }
        const int c0p = cj * 5;
        for (int idx = tid; idx < 5 * 64; idx += 256) {
            int row = idx >> 6, q = idx & 63;
            *(float4*)(sm + OP2 + row * 260 + q * 4) =
                *(const float4*)(proj2_w + (size_t)(c0p + row) * 256 + q * 4);
        }
    }
    // zero states
    {
        int i = blockIdx.x * 256 + tid;
        g_HA[0][i] = 0.f;
        g_H1[i] = 0.f;
        g_H2[i] = 0.f;
    }
    gridbar(lgen);

    float gh1[3], gh2[3];

    for (int t = 0; t < TSTEPS; t++) {
        const int p = t & 1;
        // ================= P0: attn GRU + gh1/gh2 (to regs) + prev proj2 ===
        {   // attn GRU: gh gemm + combine with precomputed gi
            load_A32(g_HA[p], b0, As);
            __syncthreads();
            float acc[3];
            gate3(As, sm + OWA, r, cg, acc);
            const int b = b0 + r;
            const float* gb = g_GIA + ((size_t)b * TSTEPS + t) * 768;
            float rr = sigm(gb[c] + acc[0] + attn_bhh[c]);
            float zz = sigm(gb[256 + c] + acc[1] + attn_bhh[256 + c]);
            float nn = tanhf(gb[512 + c] + rr * (acc[2] + attn_bhh[512 + c]));
            float hp = As[r * 260 + c];
            g_HA[p ^ 1][(size_t)b * 256 + c] = (1.f - zz) * nn + zz * hp;
            __syncthreads();
        }
        {   // gh1 = h1 @ w1hh^T + b1hh  (stays in registers)
            load_A32(g_H1, b0, As);
            __syncthreads();
            gate3(As, sm + OW1H, r, cg, gh1);
            gh1[0] += rnn1_bhh[c]; gh1[1] += rnn1_bhh[256 + c]; gh1[2] += rnn1_bhh[512 + c];
            __syncthreads();
        }
        {   // gh2
            load_A32(g_H2, b0, As);
            __syncthreads();
            gate3(As, sm + OW2H, r, cg, gh2);
            gh2[0] += rnn2_bhh[c]; gh2[1] += rnn2_bhh[256 + c]; gh2[2] += rnn2_bhh[512 + c];
            __syncthreads();
        }
        if (t > 0) {  // proj2 for t-1
            load_A32(g_Y2, b0, As);
            __syncthreads();
            const int j = tid & 7, c0p = cj * 5;
            if (j < 5) {
                const ulonglong2* a8 = (const ulonglong2*)(As + r * 260);
                const ulonglong2* w8 = (const ulonglong2*)(sm + OP2 + j * 260);
                ull acc = 0;
#pragma unroll 8
                for (int k = 0; k < 64; k++) {
                    ulonglong2 a = a8[k], w = w8[k];
                    acc = ffma2(a.x, w.x, acc); acc = ffma2(a.y, w.y, acc);
                }
                out_mel[(size_t)(b0 + r) * 80000 + (size_t)(t - 1) * 160 + c0p + j] =
                    unpack_sum(acc) + proj2_b[c0p + j];
            }
            __syncthreads();
        }
        gridbar(lgen);
        // ================= P1: attention softmax + context ==================
        {
            __shared__ float red[8];
            __shared__ float redv[2];
            const int b = blockIdx.x;
            float* q = sm + OST;
            float* sc = sm + OST + 256;
            q[tid] = g_HA[p ^ 1][(size_t)b * 256 + tid];
            __syncthreads();
            const float* ep = g_encT + (size_t)b * 65536 + tid;
            float s0 = 0.f, s1 = 0.f, s2 = 0.f, s3 = 0.f;
#pragma unroll 4
            for (int d = 0; d < 256; d += 4) {
                s0 += q[d] * ep[d * 256];
                s1 += q[d + 1] * ep[(d + 1) * 256];
                s2 += q[d + 2] * ep[(d + 2) * 256];
                s3 += q[d + 3] * ep[(d + 3) * 256];
            }
            float s = (s0 + s1) + (s2 + s3);
            float m = s;
#pragma unroll
            for (int off = 16; off > 0; off >>= 1) m = fmaxf(m, __shfl_xor_sync(~0u, m, off));
            const int w = tid >> 5;
            if ((tid & 31) == 0) red[w] = m;
            __syncthreads();
            if (tid < 8) {
                float x = red[tid];
#pragma unroll
                for (int off = 4; off > 0; off >>= 1) x = fmaxf(x, __shfl_xor_sync(0xffu, x, off));
                if (tid == 0) redv[0] = x;
            }
            __syncthreads();
            float e = expf(s - redv[0]);
            float su = e;
#pragma unroll
            for (int off = 16; off > 0; off >>= 1) su += __shfl_xor_sync(~0u, su, off);
            if ((tid & 31) == 0) red[w] = su;
            __syncthreads();
            if (tid < 8) {
                float x = red[tid];
#pragma unroll
                for (int off = 4; off > 0; off >>= 1) x += __shfl_xor_sync(0xffu, x, off);
                if (tid == 0) redv[1] = x;
            }
            __syncthreads();
            float wgt = e / redv[1];
            sc[tid] = wgt;
            g_ALN[((size_t)t * BATCH + b) * 256 + tid] = wgt;
            __syncthreads();
            const float* ep2 = enc + (size_t)b * 65536 + tid;
            float c0a = 0.f, c1a = 0.f, c2a = 0.f, c3a = 0.f;
#pragma unroll 4
            for (int l = 0; l < 256; l += 4) {
                c0a += sc[l] * ep2[l * 256];
                c1a += sc[l + 1] * ep2[(l + 1) * 256];
                c2a += sc[l + 2] * ep2[(l + 2) * 256];
                c3a += sc[l + 3] * ep2[(l + 3) * 256];
            }
            g_CTX[(size_t)b * 256 + tid] = (c0a + c1a) + (c2a + c3a);
            __syncthreads();
        }
        gridbar(lgen);
        // ================= P2: proj1 =======================================
        {
            const float* Hn = g_HA[p ^ 1];
            for (int idx = tid; idx < 32 * 128; idx += 256) {
                int rr2 = idx >> 7, q = idx & 127;
                const float* src = (q < 64) ? (g_CTX + (size_t)(b0 + rr2) * 256 + q * 4)
                                            : (Hn + (size_t)(b0 + rr2) * 256 + (q - 64) * 4);
                *(float4*)(As + rr2 * 516 + q * 4) = *(const float4*)src;
            }
            __syncthreads();
            const int rr2 = tid >> 3, j = tid & 7, n0 = cj * 8;
            const ulonglong2* a8 = (const ulonglong2*)(As + rr2 * 516);
            const ulonglong2* w8 = (const ulonglong2*)(sm + OP1 + j * 516);
            ull acc = 0;
#pragma unroll 8
            for (int k = 0; k < 128; k++) {
                ulonglong2 a = a8[k], w = w8[k];
                acc = ffma2(a.x, w.x, acc); acc = ffma2(a.y, w.y, acc);
            }
            g_DEC[(size_t)(b0 + rr2) * 256 + n0 + j] = unpack_sum(acc) + proj1_b[n0 + j];
            __syncthreads();
        }
        gridbar(lgen);
        // ================= P3: rnn1 gi + combine + residual ================
        {
            load_A32(g_DEC, b0, As);
            __syncthreads();
            float acc[3];
            gate3(As, sm + OW1I, r, cg, acc);
            const int b = b0 + r;
            float rr2 = sigm(acc[0] + rnn1_bih[c] + gh1[0]);
            float zz = sigm(acc[1] + rnn1_bih[256 + c] + gh1[1]);
            float nn = tanhf(acc[2] + rnn1_bih[512 + c] + rr2 * gh1[2]);
            float hp = g_H1[(size_t)b * 256 + c];
            float hn = (1.f - zz) * nn + zz * hp;
            g_H1[(size_t)b * 256 + c] = hn;
            g_Y1[(size_t)b * 256 + c] = As[r * 260 + c] + hn;
            __syncthreads();
        }
        gridbar(lgen);
        // ================= P4: rnn2 gi + combine + residual ================
        {
            load_A32(g_Y1, b0, As);
            __syncthreads();
            float acc[3];
            gate3(As, sm + OW2I, r, cg, acc);
            const int b = b0 + r;
            float rr2 = sigm(acc[0] + rnn2_bih[c] + gh2[0]);
            float zz = sigm(acc[1] + rnn2_bih[256 + c] + gh2[1]);
            float nn = tanhf(acc[2] + rnn2_bih[512 + c] + rr2 * gh2[2]);
            float hp = g_H2[(size_t)b * 256 + c];
            float hn = (1.f - zz) * nn + zz * hp;
            g_H2[(size_t)b * 256 + c] = hn;
            g_Y2[(size_t)b * 256 + c] = As[r * 260 + c] + hn;
            __syncthreads();
        }
        gridbar(lgen);
    }
    // final proj2 (t = TSTEPS-1)
    {
        load_A32(g_Y2, b0, As);
        __syncthreads();
        const int j = tid & 7, c0p = cj * 5;
        if (j < 5) {
            const ulonglong2* a8 = (const ulonglong2*)(As + r * 260);
            const ulonglong2* w8 = (const ulonglong2*)(sm + OP2 + j * 260);
            ull acc = 0;
#pragma unroll 8
            for (int k = 0; k < 64; k++) {
                ulonglong2 a = a8[k], w = w8[k];
                acc = ffma2(a.x, w.x, acc); acc = ffma2(a.y, w.y, acc);
            }
            out_mel[(size_t)(b0 + r) * 80000 + (size_t)(TSTEPS - 1) * 160 + c0p + j] =
                unpack_sum(acc) + proj2_b[c0p + j];
        }
    }
}

extern "C" void kernel_launch(void* const* d_in, const int* in_sizes, int n_in,
                              void* d_out, int out_size) {
    const float* dec      = (const float*)d_in[0];
    const float* enc      = (const float*)d_in[1];
    const float* pre_w1   = (const float*)d_in[2];
    const float* pre_b1   = (const float*)d_in[3];
    const float* pre_w2   = (const float*)d_in[4];
    const float* pre_b2   = (const float*)d_in[5];
    const float* attn_wih = (const float*)d_in[6];
    const float* attn_whh = (const float*)d_in[7];
    const float* attn_bih = (const float*)d_in[8];
    const float* attn_bhh = (const float*)d_in[9];
    const float* proj1_w  = (const float*)d_in[10];
    const float* proj1_b  = (const float*)d_in[11];
    const float* rnn1_wih = (const float*)d_in[12];
    const float* rnn1_whh = (const float*)d_in[13];
    const float* rnn1_bih = (const float*)d_in[14];
    const float* rnn1_bhh = (const float*)d_in[15];
    const float* rnn2_wih = (const float*)d_in[16];
    const float* rnn2_whh = (const float*)d_in[17];
    const float* rnn2_bih = (const float*)d_in[18];
    const float* rnn2_bhh = (const float*)d_in[19];
    const float* proj2_w  = (const float*)d_in[20];
    const float* proj2_b  = (const float*)d_in[21];
    float* out = (float*)d_out;

    float *x1, *x2, *gia;
    cudaGetSymbolAddress((void**)&x1, g_X1);
    cudaGetSymbolAddress((void**)&x2, g_X2);
    cudaGetSymbolAddress((void**)&gia, g_GIA);

    const int SMEM = SMEMF * 4;
    cudaFuncSetAttribute(decoder_loop, cudaFuncAttributeMaxDynamicSharedMemorySize, SMEM);

    transpose_enc_k<<<dim3(128, 8, 8), 256>>>(enc);
    gemm_k<true><<<dim3(1000, 4), 256>>>(dec, pre_w1, pre_b1, x1, 80, 256);
    gemm_k<true><<<dim3(1000, 2), 256>>>(x1, pre_w2, pre_b2, x2, 256, 128);
    gemm_k<false><<<dim3(1000, 12), 256>>>(x2, attn_wih, attn_bih, gia, 128, 768);
    decoder_loop<<<128, 256, SMEM>>>(enc, attn_whh, attn_bhh, proj1_w, proj1_b,
                                     rnn1_wih, rnn1_whh, rnn1_bih, rnn1_bhh,
                                     rnn2_wih, rnn2_whh, rnn2_bih, rnn2_bhh,
                                     proj2_w, proj2_b, out);
    transpose_aln_k<<<dim3(128, 8, 16), 256>>>(out + 10240000);
}

// round 12
// speedup vs baseline: 1.8785x; 1.2487x over previous
#include <cuda_runtime.h>
#include <cstdint>
#include <cstddef>

#define TSTEPS 500
#define BATCH  128

// smem float offsets
#define OWA  0
#define OW1I 6240
#define OW1H 12480
#define OW2I 18720
#define OW2H 24960
#define OWR  31200
#define OP2  33280
#define OST  34580
#define SMEMF 42900   /* 171,600 bytes */

__device__ float g_X1[64000 * 256];   // prenet hidden, then reused as encW [32768 x 256]
__device__ float g_X2[64000 * 128];
__device__ float g_GIA[64000 * 768];
__device__ float g_encT[128 * 256 * 256];
__device__ float g_ALN[64000 * 256];
__device__ float g_HA[2][128 * 256];
__device__ float g_H1[128 * 256];
__device__ float g_H2[128 * 256];
__device__ float g_CTX[128 * 256];
__device__ float g_DEC[128 * 256];    // hWr (+bias)
__device__ float g_Y1[128 * 256];
__device__ float g_Y2[128 * 256];
__device__ unsigned g_cnt;
__device__ unsigned g_gen;

typedef unsigned long long ull;

__device__ __forceinline__ ull ffma2(ull a, ull b, ull c) {
    ull d;
    asm("fma.rn.f32x2 %0, %1, %2, %3;" : "=l"(d) : "l"(a), "l"(b), "l"(c));
    return d;
}
__device__ __forceinline__ float unpack_sum(ull v) {
    float2 f = *(float2*)&v;
    return f.x + f.y;
}

// C[M,N] = act(A[M,K] @ Wrows^T + bias); W row n starts at W + n*ldw (+K elems used)
template <bool RELU, bool HASB>
__global__ __launch_bounds__(256) void gemm_k(const float* __restrict__ A,
                                              const float* __restrict__ W,
                                              const float* __restrict__ bias,
                                              float* __restrict__ C, int K, int N, int ldw) {
    __shared__ float As[16 * 68];
    __shared__ float Ws[16 * 68];
    const int m0 = blockIdx.x * 64, n0 = blockIdx.y * 64;
    const int tid = threadIdx.x, tx = tid & 15, ty = tid >> 4;
    float acc[4][4] = {};
    for (int k0 = 0; k0 < K; k0 += 16) {
        int idx = tid;
#pragma unroll
        for (int it = 0; it < 4; it++) {
            int m = idx >> 4, k = idx & 15;
            As[k * 68 + m] = A[(size_t)(m0 + m) * K + k0 + k];
            Ws[k * 68 + m] = W[(size_t)(n0 + m) * ldw + k0 + k];
            idx += 256;
        }
        __syncthreads();
#pragma unroll
        for (int k = 0; k < 16; k++) {
            float4 a = *(const float4*)&As[k * 68 + ty * 4];
            float4 w = *(const float4*)&Ws[k * 68 + tx * 4];
            acc[0][0] += a.x * w.x; acc[0][1] += a.x * w.y; acc[0][2] += a.x * w.z; acc[0][3] += a.x * w.w;
            acc[1][0] += a.y * w.x; acc[1][1] += a.y * w.y; acc[1][2] += a.y * w.z; acc[1][3] += a.y * w.w;
            acc[2][0] += a.z * w.x; acc[2][1] += a.z * w.y; acc[2][2] += a.z * w.z; acc[2][3] += a.z * w.w;
            acc[3][0] += a.w * w.x; acc[3][1] += a.w * w.y; acc[3][2] += a.w * w.z; acc[3][3] += a.w * w.w;
        }
        __syncthreads();
    }
#pragma unroll
    for (int i = 0; i < 4; i++) {
        int m = m0 + ty * 4 + i;
#pragma unroll
        for (int j = 0; j < 4; j++) {
            float v = acc[i][j] + (HASB ? bias[n0 + tx * 4 + j] : 0.f);
            if (RELU) v = fmaxf(v, 0.f);
            C[(size_t)m * N + n0 + tx * 4 + j] = v;
        }
    }
}

__global__ void transpose_enc_k(const float* __restrict__ enc) {
    __shared__ float tile[32][33];
    const int b = blockIdx.x, l0 = blockIdx.y * 32, d0 = blockIdx.z * 32;
    const int j = threadIdx.x & 31, i0 = threadIdx.x >> 5;
    const float* base = enc + (size_t)b * 65536;
#pragma unroll
    for (int ii = 0; ii < 32; ii += 8)
        tile[i0 + ii][j] = base[(size_t)(l0 + i0 + ii) * 256 + d0 + j];
    __syncthreads();
    float* ob = g_encT + (size_t)b * 65536;
#pragma unroll
    for (int ii = 0; ii < 32; ii += 8)
        ob[(size_t)(d0 + i0 + ii) * 256 + l0 + j] = tile[j][i0 + ii];
}

__global__ void transpose_aln_k(float* __restrict__ out) {
    __shared__ float tile[32][33];
    const int b = blockIdx.x, l0 = blockIdx.y * 32, t0 = blockIdx.z * 32;
    const int j = threadIdx.x & 31, i0 = threadIdx.x >> 5;
#pragma unroll
    for (int ii = 0; ii < 32; ii += 8) {
        int t = t0 + i0 + ii;
        if (t < TSTEPS) tile[i0 + ii][j] = g_ALN[((size_t)t * BATCH + b) * 256 + l0 + j];
    }
    __syncthreads();
#pragma unroll
    for (int ii = 0; ii < 32; ii += 8) {
        int t = t0 + j, l = l0 + i0 + ii;
        if (t < TSTEPS) out[((size_t)b * 256 + l) * TSTEPS + t] = tile[j][i0 + ii];
    }
}

__device__ __forceinline__ float sigm(float x) { return 1.f / (1.f + expf(-x)); }

__device__ __forceinline__ void gridbar(unsigned& lgen) {
    __syncthreads();
    lgen++;
    if (threadIdx.x == 0) {
        unsigned old;
        asm volatile("atom.add.acq_rel.gpu.global.u32 %0, [%1], 1;"
                     : "=r"(old) : "l"(&g_cnt) : "memory");
        if (old == gridDim.x - 1) {
            g_cnt = 0;
            asm volatile("st.release.gpu.global.u32 [%0], %1;"
                         :: "l"(&g_gen), "r"(lgen) : "memory");
        } else {
            unsigned g;
            do {
                asm volatile("ld.acquire.gpu.global.u32 %0, [%1];"
                             : "=r"(g) : "l"(&g_gen) : "memory");
            } while ((int)(g - lgen) < 0);
        }
    }
    __syncthreads();
}

__device__ __forceinline__ void load_A32(const float* __restrict__ src, int b0, float* As) {
    for (int idx = threadIdx.x; idx < 32 * 64; idx += 256) {
        int r = idx >> 6, q = idx & 63;
        *(float4*)(As + r * 260 + q * 4) = *(const float4*)(src + (size_t)(b0 + r) * 256 + q * 4);
    }
}

// As = srcA + srcB (elementwise), 32 rows
__device__ __forceinline__ void load_A32sum(const float* __restrict__ sa,
                                            const float* __restrict__ sb, int b0, float* As) {
    for (int idx = threadIdx.x; idx < 32 * 64; idx += 256) {
        int r = idx >> 6, q = idx & 63;
        float4 a = *(const float4*)(sa + (size_t)(b0 + r) * 256 + q * 4);
        float4 b = *(const float4*)(sb + (size_t)(b0 + r) * 256 + q * 4);
        a.x += b.x; a.y += b.y; a.z += b.z; a.w += b.w;
        *(float4*)(As + r * 260 + q * 4) = a;
    }
}

__device__ __forceinline__ void preload_W24(const float* __restrict__ w, int c0, float* Wd) {
    for (int idx = threadIdx.x; idx < 24 * 64; idx += 256) {
        int row = idx >> 6, q = idx & 63;
        int g = row >> 3, i = row & 7;
        *(float4*)(Wd + row * 260 + q * 4) =
            *(const float4*)(w + (size_t)(g * 256 + c0 + i) * 256 + q * 4);
    }
}

__device__ __forceinline__ void gate3(const float* As, const float* Ws, int r, int cg, float out[3]) {
    const ulonglong2* a8 = (const ulonglong2*)(As + r * 260);
    const ulonglong2* w0 = (const ulonglong2*)(Ws + cg * 260);
    const ulonglong2* w1 = (const ulonglong2*)(Ws + (8 + cg) * 260);
    const ulonglong2* w2 = (const ulonglong2*)(Ws + (16 + cg) * 260);
    ull acc0 = 0, acc1 = 0, acc2 = 0;
#pragma unroll 8
    for (int k = 0; k < 64; k++) {
        ulonglong2 a = a8[k];
        ulonglong2 b0 = w0[k], b1 = w1[k], b2 = w2[k];
        acc0 = ffma2(a.x, b0.x, acc0); acc0 = ffma2(a.y, b0.y, acc0);
        acc1 = ffma2(a.x, b1.x, acc1); acc1 = ffma2(a.y, b1.y, acc1);
        acc2 = ffma2(a.x, b2.x, acc2); acc2 = ffma2(a.y, b2.y, acc2);
    }
    out[0] = unpack_sum(acc0);
    out[1] = unpack_sum(acc1);
    out[2] = unpack_sum(acc2);
}

__global__ __launch_bounds__(256) void decoder_loop(
    const float* __restrict__ attn_bhh,
    const float* __restrict__ proj1_b,
    const float* __restrict__ rnn1_bih, const float* __restrict__ rnn1_bhh,
    const float* __restrict__ rnn2_bih, const float* __restrict__ rnn2_bhh,
    const float* __restrict__ attn_whh,
    const float* __restrict__ proj1_w,
    const float* __restrict__ rnn1_wih, const float* __restrict__ rnn1_whh,
    const float* __restrict__ rnn2_wih, const float* __restrict__ rnn2_whh,
    const float* __restrict__ proj2_w, const float* __restrict__ proj2_b,
    float* __restrict__ out_mel) {
    extern __shared__ float sm[];
    unsigned lgen;
    asm volatile("ld.acquire.gpu.global.u32 %0, [%1];" : "=r"(lgen) : "l"(&g_gen) : "memory");
    const int tid = threadIdx.x;
    const int bb = blockIdx.x >> 5, cj = blockIdx.x & 31;
    const int b0 = bb * 32, c0 = cj * 8;
    const int r = tid >> 3, cg = tid & 7, c = c0 + cg;
    float* As = sm + OST;

    // preload resident weights
    preload_W24(attn_whh, c0, sm + OWA);
    preload_W24(rnn1_wih, c0, sm + OW1I);
    preload_W24(rnn1_whh, c0, sm + OW1H);
    preload_W24(rnn2_wih, c0, sm + OW2I);
    preload_W24(rnn2_whh, c0, sm + OW2H);
    for (int idx = tid; idx < 8 * 64; idx += 256) {   // Wr = proj1_w[:, 256:512] slice
        int row = idx >> 6, q = idx & 63;
        *(float4*)(sm + OWR + row * 260 + q * 4) =
            *(const float4*)(proj1_w + (size_t)(c0 + row) * 512 + 256 + q * 4);
    }
    for (int idx = tid; idx < 5 * 64; idx += 256) {
        int row = idx >> 6, q = idx & 63;
        *(float4*)(sm + OP2 + row * 260 + q * 4) =
            *(const float4*)(proj2_w + (size_t)(cj * 5 + row) * 256 + q * 4);
    }
    // prologue: zero states, hA(0)=attnGRU(0, gia(0)), gh1(0)=b1hh
    {
        int i = blockIdx.x * 256 + tid;
        g_H1[i] = 0.f;
        g_H2[i] = 0.f;
        const int b = b0 + r;
        const float* gb = g_GIA + ((size_t)b * TSTEPS) * 768;
        float rr = sigm(gb[c] + attn_bhh[c]);
        float zz = sigm(gb[256 + c] + attn_bhh[256 + c]);
        float nn = tanhf(gb[512 + c] + rr * attn_bhh[512 + c]);
        g_HA[0][(size_t)b * 256 + c] = (1.f - zz) * nn;
    }
    float gh1[3] = { rnn1_bhh[c], rnn1_bhh[256 + c], rnn1_bhh[512 + c] };
    float gh2[3];
    gridbar(lgen);

    for (int t = 0; t < TSTEPS; t++) {
        const int p = t & 1;
        // ============ X: attention (align + ctxW) + attnGRU(t+1) + hWr =====
        {
            __shared__ float red[8];
            __shared__ float redv[2];
            const int b = blockIdx.x;
            float* q = sm + OST;
            float* sc = sm + OST + 256;
            q[tid] = g_HA[p][(size_t)b * 256 + tid];
            __syncthreads();
            const float* ep = g_encT + (size_t)b * 65536 + tid;
            float s0 = 0.f, s1 = 0.f, s2 = 0.f, s3 = 0.f;
#pragma unroll 4
            for (int d = 0; d < 256; d += 4) {
                s0 += q[d] * ep[d * 256];
                s1 += q[d + 1] * ep[(d + 1) * 256];
                s2 += q[d + 2] * ep[(d + 2) * 256];
                s3 += q[d + 3] * ep[(d + 3) * 256];
            }
            float s = (s0 + s1) + (s2 + s3);
            float m = s;
#pragma unroll
            for (int off = 16; off > 0; off >>= 1) m = fmaxf(m, __shfl_xor_sync(~0u, m, off));
            const int w = tid >> 5;
            if ((tid & 31) == 0) red[w] = m;
            __syncthreads();
            if (tid < 8) {
                float x = red[tid];
#pragma unroll
                for (int off = 4; off > 0; off >>= 1) x = fmaxf(x, __shfl_xor_sync(0xffu, x, off));
                if (tid == 0) redv[0] = x;
            }
            __syncthreads();
            float e = expf(s - redv[0]);
            float su = e;
#pragma unroll
            for (int off = 16; off > 0; off >>= 1) su += __shfl_xor_sync(~0u, su, off);
            if ((tid & 31) == 0) red[w] = su;
            __syncthreads();
            if (tid < 8) {
                float x = red[tid];
#pragma unroll
                for (int off = 4; off > 0; off >>= 1) x += __shfl_xor_sync(0xffu, x, off);
                if (tid == 0) redv[1] = x;
            }
            __syncthreads();
            float wgt = e / redv[1];
            sc[tid] = wgt;
            g_ALN[((size_t)t * BATCH + b) * 256 + tid] = wgt;
            __syncthreads();
            const float* ew = g_X1 + (size_t)b * 65536 + tid;   // encW
            float c0a = 0.f, c1a = 0.f, c2a = 0.f, c3a = 0.f;
#pragma unroll 4
            for (int l = 0; l < 256; l += 4) {
                c0a += sc[l] * ew[l * 256];
                c1a += sc[l + 1] * ew[(l + 1) * 256];
                c2a += sc[l + 2] * ew[(l + 2) * 256];
                c3a += sc[l + 3] * ew[(l + 3) * 256];
            }
            g_CTX[(size_t)b * 256 + tid] = (c0a + c1a) + (c2a + c3a);
            __syncthreads();
        }
        load_A32(g_HA[p], b0, As);   // hA(t) for attnGRU + hWr
        __syncthreads();
        if (t < TSTEPS - 1) {        // attnGRU -> hA(t+1)
            float acc[3];
            gate3(As, sm + OWA, r, cg, acc);
            const int b = b0 + r;
            const float* gb = g_GIA + ((size_t)b * TSTEPS + t + 1) * 768;
            float rr = sigm(gb[c] + acc[0] + attn_bhh[c]);
            float zz = sigm(gb[256 + c] + acc[1] + attn_bhh[256 + c]);
            float nn = tanhf(gb[512 + c] + rr * (acc[2] + attn_bhh[512 + c]));
            float hp = As[r * 260 + c];
            g_HA[p ^ 1][(size_t)b * 256 + c] = (1.f - zz) * nn + zz * hp;
        }
        {   // hWr = hA(t) @ Wr^T + b1
            const ulonglong2* a8 = (const ulonglong2*)(As + r * 260);
            const ulonglong2* w8 = (const ulonglong2*)(sm + OWR + cg * 260);
            ull acc = 0;
#pragma unroll 8
            for (int k = 0; k < 64; k++) {
                ulonglong2 a = a8[k], w = w8[k];
                acc = ffma2(a.x, w.x, acc); acc = ffma2(a.y, w.y, acc);
            }
            g_DEC[(size_t)(b0 + r) * 256 + c] = unpack_sum(acc) + proj1_b[c];
        }
        gridbar(lgen);
        // ============ Y: rnn1 + gh2(t) + proj2(t-1) ========================
        load_A32sum(g_CTX, g_DEC, b0, As);   // decin
        __syncthreads();
        {
            float acc[3];
            gate3(As, sm + OW1I, r, cg, acc);
            const int b = b0 + r;
            float rr = sigm(acc[0] + rnn1_bih[c] + gh1[0]);
            float zz = sigm(acc[1] + rnn1_bih[256 + c] + gh1[1]);
            float nn = tanhf(acc[2] + rnn1_bih[512 + c] + rr * gh1[2]);
            float hp = g_H1[(size_t)b * 256 + c];
            float hn = (1.f - zz) * nn + zz * hp;
            g_H1[(size_t)b * 256 + c] = hn;
            g_Y1[(size_t)b * 256 + c] = As[r * 260 + c] + hn;
        }
        __syncthreads();
        load_A32(g_H2, b0, As);              // h2(t-1)
        __syncthreads();
        gate3(As, sm + OW2H, r, cg, gh2);
        gh2[0] += rnn2_bhh[c]; gh2[1] += rnn2_bhh[256 + c]; gh2[2] += rnn2_bhh[512 + c];
        __syncthreads();
        if (t > 0) {                         // proj2 of t-1
            load_A32(g_Y2, b0, As);
            __syncthreads();
            const int j = tid & 7, c0p = cj * 5;
            if (j < 5) {
                const ulonglong2* a8 = (const ulonglong2*)(As + r * 260);
                const ulonglong2* w8 = (const ulonglong2*)(sm + OP2 + j * 260);
                ull acc = 0;
#pragma unroll 8
                for (int k = 0; k < 64; k++) {
                    ulonglong2 a = a8[k], w = w8[k];
                    acc = ffma2(a.x, w.x, acc); acc = ffma2(a.y, w.y, acc);
                }
                out_mel[(size_t)(b0 + r) * 80000 + (size_t)(t - 1) * 160 + c0p + j] =
                    unpack_sum(acc) + proj2_b[c0p + j];
            }
        }
        gridbar(lgen);
        // ============ Z: rnn2 + gh1(t+1) ===================================
        load_A32(g_Y1, b0, As);
        __syncthreads();
        {
            float acc[3];
            gate3(As, sm + OW2I, r, cg, acc);
            const int b = b0 + r;
            float rr = sigm(acc[0] + rnn2_bih[c] + gh2[0]);
            float zz = sigm(acc[1] + rnn2_bih[256 + c] + gh2[1]);
            float nn = tanhf(acc[2] + rnn2_bih[512 + c] + rr * gh2[2]);
            float hp = g_H2[(size_t)b * 256 + c];
            float hn = (1.f - zz) * nn + zz * hp;
            g_H2[(size_t)b * 256 + c] = hn;
            g_Y2[(size_t)b * 256 + c] = As[r * 260 + c] + hn;
        }
        __syncthreads();
        load_A32(g_H1, b0, As);              // h1(t) final
        __syncthreads();
        gate3(As, sm + OW1H, r, cg, gh1);
        gh1[0] += rnn1_bhh[c]; gh1[1] += rnn1_bhh[256 + c]; gh1[2] += rnn1_bhh[512 + c];
        gridbar(lgen);
    }
    // final proj2 (t = TSTEPS-1)
    load_A32(g_Y2, b0, As);
    __syncthreads();
    {
        const int j = tid & 7, c0p = cj * 5;
        if (j < 5) {
            const ulonglong2* a8 = (const ulonglong2*)(As + r * 260);
            const ulonglong2* w8 = (const ulonglong2*)(sm + OP2 + j * 260);
            ull acc = 0;
#pragma unroll 8
            for (int k = 0; k < 64; k++) {
                ulonglong2 a = a8[k], w = w8[k];
                acc = ffma2(a.x, w.x, acc); acc = ffma2(a.y, w.y, acc);
            }
            out_mel[(size_t)(b0 + r) * 80000 + (size_t)(TSTEPS - 1) * 160 + c0p + j] =
                unpack_sum(acc) + proj2_b[c0p + j];
        }
    }
}

extern "C" void kernel_launch(void* const* d_in, const int* in_sizes, int n_in,
                              void* d_out, int out_size) {
    const float* dec      = (const float*)d_in[0];
    const float* enc      = (const float*)d_in[1];
    const float* pre_w1   = (const float*)d_in[2];
    const float* pre_b1   = (const float*)d_in[3];
    const float* pre_w2   = (const float*)d_in[4];
    const float* pre_b2   = (const float*)d_in[5];
    const float* attn_wih = (const float*)d_in[6];
    const float* attn_whh = (const float*)d_in[7];
    const float* attn_bih = (const float*)d_in[8];
    const float* attn_bhh = (const float*)d_in[9];
    const float* proj1_w  = (const float*)d_in[10];
    const float* proj1_b  = (const float*)d_in[11];
    const float* rnn1_wih = (const float*)d_in[12];
    const float* rnn1_whh = (const float*)d_in[13];
    const float* rnn1_bih = (const float*)d_in[14];
    const float* rnn1_bhh = (const float*)d_in[15];
    const float* rnn2_wih = (const float*)d_in[16];
    const float* rnn2_whh = (const float*)d_in[17];
    const float* rnn2_bih = (const float*)d_in[18];
    const float* rnn2_bhh = (const float*)d_in[19];
    const float* proj2_w  = (const float*)d_in[20];
    const float* proj2_b  = (const float*)d_in[21];
    float* out = (float*)d_out;

    float *x1, *x2, *gia;
    cudaGetSymbolAddress((void**)&x1, g_X1);
    cudaGetSymbolAddress((void**)&x2, g_X2);
    cudaGetSymbolAddress((void**)&gia, g_GIA);

    const int SMEM = SMEMF * 4;
    cudaFuncSetAttribute(decoder_loop, cudaFuncAttributeMaxDynamicSharedMemorySize, SMEM);

    transpose_enc_k<<<dim3(128, 8, 8), 256>>>(enc);
    // prenet + attention gi (uses g_X1 as scratch for prenet hidden)
    gemm_k<true, true><<<dim3(1000, 4), 256>>>(dec, pre_w1, pre_b1, x1, 80, 256, 80);
    gemm_k<true, true><<<dim3(1000, 2), 256>>>(x1, pre_w2, pre_b2, x2, 256, 128, 256);
    gemm_k<false, true><<<dim3(1000, 12), 256>>>(x2, attn_wih, attn_bih, gia, 128, 768, 128);
    // encW = enc @ proj1_w[:, :256]^T  (g_X1 reused as encW)
    gemm_k<false, false><<<dim3(512, 4), 256>>>(enc, proj1_w, nullptr, x1, 256, 256, 512);
    decoder_loop<<<128, 256, SMEM>>>(attn_bhh, proj1_b,
                                     rnn1_bih, rnn1_bhh, rnn2_bih, rnn2_bhh,
                                     attn_whh, proj1_w,
                                     rnn1_wih, rnn1_whh, rnn2_wih, rnn2_whh,
                                     proj2_w, proj2_b, out);
    transpose_aln_k<<<dim3(128, 8, 16), 256>>>(out + 10240000);
}

// round 13
// speedup vs baseline: 1.9432x; 1.0345x over previous
#include <cuda_runtime.h>
#include <cstdint>
#include <cstddef>

#define TSTEPS 500
#define BATCH  128

// smem float offsets
#define OWA  0
#define OW1I 6240
#define OW1H 12480
#define OW2I 18720
#define OW2H 24960
#define OWR  31200
#define OP2  33280
#define OST  34580
#define SMEMF 42900   /* 171,600 bytes */

__device__ float g_X1[64000 * 256];   // prenet hidden, then reused as encW
__device__ float g_X2[64000 * 128];
__device__ float g_GIA[64000 * 768];
__device__ float g_encT[128 * 256 * 256];
__device__ float g_ALN[64000 * 256];
__device__ float g_HA[2][128 * 256];
__device__ float g_H1[128 * 256];
__device__ float g_H2[128 * 256];
__device__ float g_CTX[128 * 256];
__device__ float g_DEC[128 * 256];
__device__ float g_Y1[128 * 256];
__device__ float g_Y2[128 * 256];
__device__ unsigned g_flag[128 * 32];  // one 128B line per CTA
__device__ unsigned g_gen;

typedef unsigned long long ull;

__device__ __forceinline__ ull ffma2(ull a, ull b, ull c) {
    ull d;
    asm("fma.rn.f32x2 %0, %1, %2, %3;" : "=l"(d) : "l"(a), "l"(b), "l"(c));
    return d;
}
__device__ __forceinline__ float unpack_sum(ull v) {
    float2 f = *(float2*)&v;
    return f.x + f.y;
}

template <bool RELU, bool HASB>
__global__ __launch_bounds__(256) void gemm_k(const float* __restrict__ A,
                                              const float* __restrict__ W,
                                              const float* __restrict__ bias,
                                              float* __restrict__ C, int K, int N, int ldw) {
    __shared__ float As[16 * 68];
    __shared__ float Ws[16 * 68];
    const int m0 = blockIdx.x * 64, n0 = blockIdx.y * 64;
    const int tid = threadIdx.x, tx = tid & 15, ty = tid >> 4;
    float acc[4][4] = {};
    for (int k0 = 0; k0 < K; k0 += 16) {
        int idx = tid;
#pragma unroll
        for (int it = 0; it < 4; it++) {
            int m = idx >> 4, k = idx & 15;
            As[k * 68 + m] = A[(size_t)(m0 + m) * K + k0 + k];
            Ws[k * 68 + m] = W[(size_t)(n0 + m) * ldw + k0 + k];
            idx += 256;
        }
        __syncthreads();
#pragma unroll
        for (int k = 0; k < 16; k++) {
            float4 a = *(const float4*)&As[k * 68 + ty * 4];
            float4 w = *(const float4*)&Ws[k * 68 + tx * 4];
            acc[0][0] += a.x * w.x; acc[0][1] += a.x * w.y; acc[0][2] += a.x * w.z; acc[0][3] += a.x * w.w;
            acc[1][0] += a.y * w.x; acc[1][1] += a.y * w.y; acc[1][2] += a.y * w.z; acc[1][3] += a.y * w.w;
            acc[2][0] += a.z * w.x; acc[2][1] += a.z * w.y; acc[2][2] += a.z * w.z; acc[2][3] += a.z * w.w;
            acc[3][0] += a.w * w.x; acc[3][1] += a.w * w.y; acc[3][2] += a.w * w.z; acc[3][3] += a.w * w.w;
        }
        __syncthreads();
    }
#pragma unroll
    for (int i = 0; i < 4; i++) {
        int m = m0 + ty * 4 + i;
#pragma unroll
        for (int j = 0; j < 4; j++) {
            float v = acc[i][j] + (HASB ? bias[n0 + tx * 4 + j] : 0.f);
            if (RELU) v = fmaxf(v, 0.f);
            C[(size_t)m * N + n0 + tx * 4 + j] = v;
        }
    }
}

__global__ void transpose_enc_k(const float* __restrict__ enc) {
    __shared__ float tile[32][33];
    const int b = blockIdx.x, l0 = blockIdx.y * 32, d0 = blockIdx.z * 32;
    const int j = threadIdx.x & 31, i0 = threadIdx.x >> 5;
    const float* base = enc + (size_t)b * 65536;
#pragma unroll
    for (int ii = 0; ii < 32; ii += 8)
        tile[i0 + ii][j] = base[(size_t)(l0 + i0 + ii) * 256 + d0 + j];
    __syncthreads();
    float* ob = g_encT + (size_t)b * 65536;
#pragma unroll
    for (int ii = 0; ii < 32; ii += 8)
        ob[(size_t)(d0 + i0 + ii) * 256 + l0 + j] = tile[j][i0 + ii];
}

__global__ void transpose_aln_k(float* __restrict__ out) {
    __shared__ float tile[32][33];
    const int b = blockIdx.x, l0 = blockIdx.y * 32, t0 = blockIdx.z * 32;
    const int j = threadIdx.x & 31, i0 = threadIdx.x >> 5;
#pragma unroll
    for (int ii = 0; ii < 32; ii += 8) {
        int t = t0 + i0 + ii;
        if (t < TSTEPS) tile[i0 + ii][j] = g_ALN[((size_t)t * BATCH + b) * 256 + l0 + j];
    }
    __syncthreads();
#pragma unroll
    for (int ii = 0; ii < 32; ii += 8) {
        int t = t0 + j, l = l0 + i0 + ii;
        if (t < TSTEPS) out[((size_t)b * 256 + l) * TSTEPS + t] = tile[j][i0 + ii];
    }
}

__device__ __forceinline__ float sigm(float x) { return 1.f / (1.f + expf(-x)); }

// contention-free flag barrier: no atomics; CTA0 is the master.
__device__ __forceinline__ void gridbar(unsigned& lgen) {
    __syncthreads();
    lgen++;
    if (blockIdx.x == 0) {
        if (threadIdx.x > 0 && threadIdx.x < 128) {
            const unsigned* f = &g_flag[threadIdx.x * 32];
            unsigned v;
            do {
                asm volatile("ld.acquire.gpu.global.u32 %0, [%1];" : "=r"(v) : "l"(f) : "memory");
            } while ((int)(v - lgen) < 0);
        }
        __syncthreads();
        if (threadIdx.x == 0)
            asm volatile("st.release.gpu.global.u32 [%0], %1;" :: "l"(&g_gen), "r"(lgen) : "memory");
    } else {
        if (threadIdx.x == 0) {
            asm volatile("st.release.gpu.global.u32 [%0], %1;"
                         :: "l"(&g_flag[blockIdx.x * 32]), "r"(lgen) : "memory");
            unsigned v;
            do {
                asm volatile("ld.acquire.gpu.global.u32 %0, [%1];" : "=r"(v) : "l"(&g_gen) : "memory");
            } while ((int)(v - lgen) < 0);
        }
        __syncthreads();
    }
}

__device__ __forceinline__ void load_A32(const float* __restrict__ src, int b0, float* As) {
    for (int idx = threadIdx.x; idx < 32 * 64; idx += 256) {
        int r = idx >> 6, q = idx & 63;
        *(float4*)(As + r * 260 + q * 4) = *(const float4*)(src + (size_t)(b0 + r) * 256 + q * 4);
    }
}

__device__ __forceinline__ void load_A32sum(const float* __restrict__ sa,
                                            const float* __restrict__ sb, int b0, float* As) {
    for (int idx = threadIdx.x; idx < 32 * 64; idx += 256) {
        int r = idx >> 6, q = idx & 63;
        float4 a = *(const float4*)(sa + (size_t)(b0 + r) * 256 + q * 4);
        float4 b = *(const float4*)(sb + (size_t)(b0 + r) * 256 + q * 4);
        a.x += b.x; a.y += b.y; a.z += b.z; a.w += b.w;
        *(float4*)(As + r * 260 + q * 4) = a;
    }
}

__device__ __forceinline__ void preload_W24(const float* __restrict__ w, int c0, float* Wd) {
    for (int idx = threadIdx.x; idx < 24 * 64; idx += 256) {
        int row = idx >> 6, q = idx & 63;
        int g = row >> 3, i = row & 7;
        *(float4*)(Wd + row * 260 + q * 4) =
            *(const float4*)(w + (size_t)(g * 256 + c0 + i) * 256 + q * 4);
    }
}

__device__ __forceinline__ void gate3(const float* As, const float* Ws, int r, int cg, float out[3]) {
    const ulonglong2* a8 = (const ulonglong2*)(As + r * 260);
    const ulonglong2* w0 = (const ulonglong2*)(Ws + cg * 260);
    const ulonglong2* w1 = (const ulonglong2*)(Ws + (8 + cg) * 260);
    const ulonglong2* w2 = (const ulonglong2*)(Ws + (16 + cg) * 260);
    ull acc0 = 0, acc1 = 0, acc2 = 0;
#pragma unroll 8
    for (int k = 0; k < 64; k++) {
        ulonglong2 a = a8[k];
        ulonglong2 b0 = w0[k], b1 = w1[k], b2 = w2[k];
        acc0 = ffma2(a.x, b0.x, acc0); acc0 = ffma2(a.y, b0.y, acc0);
        acc1 = ffma2(a.x, b1.x, acc1); acc1 = ffma2(a.y, b1.y, acc1);
        acc2 = ffma2(a.x, b2.x, acc2); acc2 = ffma2(a.y, b2.y, acc2);
    }
    out[0] = unpack_sum(acc0);
    out[1] = unpack_sum(acc1);
    out[2] = unpack_sum(acc2);
}

// X-part: attention(ta) + attnGRU -> hA(ta+1) + hWr(ta)
__device__ void phase_X(int ta, const float* __restrict__ attn_bhh,
                        const float* __restrict__ proj1_b,
                        int b0, int c0, int r, int cg, int c, float* sm) {
    const int tid = threadIdx.x;
    const int p = ta & 1;
    float* As = sm + OST;
    {
        __shared__ float red[8];
        __shared__ float redv[2];
        const int b = blockIdx.x;
        float* q = sm + OST;
        float* sc = sm + OST + 256;
        q[tid] = g_HA[p][(size_t)b * 256 + tid];
        __syncthreads();
        const float* ep = g_encT + (size_t)b * 65536 + tid;
        float s0 = 0.f, s1 = 0.f, s2 = 0.f, s3 = 0.f;
#pragma unroll 4
        for (int d = 0; d < 256; d += 4) {
            s0 += q[d] * ep[d * 256];
            s1 += q[d + 1] * ep[(d + 1) * 256];
            s2 += q[d + 2] * ep[(d + 2) * 256];
            s3 += q[d + 3] * ep[(d + 3) * 256];
        }
        float s = (s0 + s1) + (s2 + s3);
        float m = s;
#pragma unroll
        for (int off = 16; off > 0; off >>= 1) m = fmaxf(m, __shfl_xor_sync(~0u, m, off));
        const int w = tid >> 5;
        if ((tid & 31) == 0) red[w] = m;
        __syncthreads();
        if (tid < 8) {
            float x = red[tid];
#pragma unroll
            for (int off = 4; off > 0; off >>= 1) x = fmaxf(x, __shfl_xor_sync(0xffu, x, off));
            if (tid == 0) redv[0] = x;
        }
        __syncthreads();
        float e = expf(s - redv[0]);
        float su = e;
#pragma unroll
        for (int off = 16; off > 0; off >>= 1) su += __shfl_xor_sync(~0u, su, off);
        if ((tid & 31) == 0) red[w] = su;
        __syncthreads();
        if (tid < 8) {
            float x = red[tid];
#pragma unroll
            for (int off = 4; off > 0; off >>= 1) x += __shfl_xor_sync(0xffu, x, off);
            if (tid == 0) redv[1] = x;
        }
        __syncthreads();
        float wgt = e / redv[1];
        sc[tid] = wgt;
        g_ALN[((size_t)ta * BATCH + b) * 256 + tid] = wgt;
        __syncthreads();
        const float* ew = g_X1 + (size_t)b * 65536 + tid;   // encW
        float c0a = 0.f, c1a = 0.f, c2a = 0.f, c3a = 0.f;
#pragma unroll 4
        for (int l = 0; l < 256; l += 4) {
            c0a += sc[l] * ew[l * 256];
            c1a += sc[l + 1] * ew[(l + 1) * 256];
            c2a += sc[l + 2] * ew[(l + 2) * 256];
            c3a += sc[l + 3] * ew[(l + 3) * 256];
        }
        g_CTX[(size_t)b * 256 + tid] = (c0a + c1a) + (c2a + c3a);
        __syncthreads();
    }
    load_A32(g_HA[p], b0, As);
    __syncthreads();
    if (ta + 1 < TSTEPS) {
        float acc[3];
        gate3(As, sm + OWA, r, cg, acc);
        const int b = b0 + r;
        const float* gb = g_GIA + ((size_t)b * TSTEPS + ta + 1) * 768;
        float rr = sigm(gb[c] + acc[0] + attn_bhh[c]);
        float zz = sigm(gb[256 + c] + acc[1] + attn_bhh[256 + c]);
        float nn = tanhf(gb[512 + c] + rr * (acc[2] + attn_bhh[512 + c]));
        float hp = As[r * 260 + c];
        g_HA[p ^ 1][(size_t)b * 256 + c] = (1.f - zz) * nn + zz * hp;
    }
    {   // hWr(ta)
        const ulonglong2* a8 = (const ulonglong2*)(As + r * 260);
        const ulonglong2* w8 = (const ulonglong2*)(sm + OWR + cg * 260);
        ull acc = 0;
#pragma unroll 8
        for (int k = 0; k < 64; k++) {
            ulonglong2 a = a8[k], w = w8[k];
            acc = ffma2(a.x, w.x, acc); acc = ffma2(a.y, w.y, acc);
        }
        g_DEC[(size_t)(b0 + r) * 256 + c] = unpack_sum(acc) + proj1_b[c];
    }
}

__global__ __launch_bounds__(256) void decoder_loop(
    const float* __restrict__ attn_bhh,
    const float* __restrict__ proj1_b,
    const float* __restrict__ rnn1_bih, const float* __restrict__ rnn1_bhh,
    const float* __restrict__ rnn2_bih, const float* __restrict__ rnn2_bhh,
    const float* __restrict__ attn_whh,
    const float* __restrict__ proj1_w,
    const float* __restrict__ rnn1_wih, const float* __restrict__ rnn1_whh,
    const float* __restrict__ rnn2_wih, const float* __restrict__ rnn2_whh,
    const float* __restrict__ proj2_w, const float* __restrict__ proj2_b,
    float* __restrict__ out_mel) {
    extern __shared__ float sm[];
    unsigned lgen;
    asm volatile("ld.acquire.gpu.global.u32 %0, [%1];" : "=r"(lgen) : "l"(&g_gen) : "memory");
    const int tid = threadIdx.x;
    const int bb = blockIdx.x >> 5, cj = blockIdx.x & 31;
    const int b0 = bb * 32, c0 = cj * 8;
    const int r = tid >> 3, cg = tid & 7, c = c0 + cg;
    float* As = sm + OST;

    preload_W24(attn_whh, c0, sm + OWA);
    preload_W24(rnn1_wih, c0, sm + OW1I);
    preload_W24(rnn1_whh, c0, sm + OW1H);
    preload_W24(rnn2_wih, c0, sm + OW2I);
    preload_W24(rnn2_whh, c0, sm + OW2H);
    for (int idx = tid; idx < 8 * 64; idx += 256) {
        int row = idx >> 6, q = idx & 63;
        *(float4*)(sm + OWR + row * 260 + q * 4) =
            *(const float4*)(proj1_w + (size_t)(c0 + row) * 512 + 256 + q * 4);
    }
    for (int idx = tid; idx < 5 * 64; idx += 256) {
        int row = idx >> 6, q = idx & 63;
        *(float4*)(sm + OP2 + row * 260 + q * 4) =
            *(const float4*)(proj2_w + (size_t)(cj * 5 + row) * 256 + q * 4);
    }
    // prologue: zero states, hA(0) = attnGRU(0, gia(0))
    {
        int i = blockIdx.x * 256 + tid;
        g_H1[i] = 0.f;
        g_H2[i] = 0.f;
        const int b = b0 + r;
        const float* gb = g_GIA + ((size_t)b * TSTEPS) * 768;
        float rr = sigm(gb[c] + attn_bhh[c]);
        float zz = sigm(gb[256 + c] + attn_bhh[256 + c]);
        float nn = tanhf(gb[512 + c] + rr * attn_bhh[512 + c]);
        g_HA[0][(size_t)b * 256 + c] = (1.f - zz) * nn;
    }
    float gh1[3] = { rnn1_bhh[c], rnn1_bhh[256 + c], rnn1_bhh[512 + c] };
    float gh2[3];
    gridbar(lgen);
    // X(0): attention(0) + attnGRU->hA(1) + hWr(0)
    phase_X(0, attn_bhh, proj1_b, b0, c0, r, cg, c, sm);
    gridbar(lgen);

    for (int t = 0; t < TSTEPS; t++) {
        // ===== A(t): rnn1 + gh2(t) + proj2(t-1) =====
        load_A32sum(g_CTX, g_DEC, b0, As);
        __syncthreads();
        {
            float acc[3];
            gate3(As, sm + OW1I, r, cg, acc);
            const int b = b0 + r;
            float rr = sigm(acc[0] + rnn1_bih[c] + gh1[0]);
            float zz = sigm(acc[1] + rnn1_bih[256 + c] + gh1[1]);
            float nn = tanhf(acc[2] + rnn1_bih[512 + c] + rr * gh1[2]);
            float hp = g_H1[(size_t)b * 256 + c];
            float hn = (1.f - zz) * nn + zz * hp;
            g_H1[(size_t)b * 256 + c] = hn;
            g_Y1[(size_t)b * 256 + c] = As[r * 260 + c] + hn;
        }
        __syncthreads();
        load_A32(g_H2, b0, As);
        __syncthreads();
        gate3(As, sm + OW2H, r, cg, gh2);
        gh2[0] += rnn2_bhh[c]; gh2[1] += rnn2_bhh[256 + c]; gh2[2] += rnn2_bhh[512 + c];
        __syncthreads();
        if (t > 0) {
            load_A32(g_Y2, b0, As);
            __syncthreads();
            const int j = tid & 7, c0p = cj * 5;
            if (j < 5) {
                const ulonglong2* a8 = (const ulonglong2*)(As + r * 260);
                const ulonglong2* w8 = (const ulonglong2*)(sm + OP2 + j * 260);
                ull acc = 0;
#pragma unroll 8
                for (int k = 0; k < 64; k++) {
                    ulonglong2 a = a8[k], w = w8[k];
                    acc = ffma2(a.x, w.x, acc); acc = ffma2(a.y, w.y, acc);
                }
                out_mel[(size_t)(b0 + r) * 80000 + (size_t)(t - 1) * 160 + c0p + j] =
                    unpack_sum(acc) + proj2_b[c0p + j];
            }
        }
        gridbar(lgen);
        // ===== B(t): rnn2(t) + gh1(t+1) + X(t+1) =====
        load_A32(g_Y1, b0, As);
        __syncthreads();
        {
            float acc[3];
            gate3(As, sm + OW2I, r, cg, acc);
            const int b = b0 + r;
            float rr = sigm(acc[0] + rnn2_bih[c] + gh2[0]);
            float zz = sigm(acc[1] + rnn2_bih[256 + c] + gh2[1]);
            float nn = tanhf(acc[2] + rnn2_bih[512 + c] + rr * gh2[2]);
            float hp = g_H2[(size_t)b * 256 + c];
            float hn = (1.f - zz) * nn + zz * hp;
            g_H2[(size_t)b * 256 + c] = hn;
            g_Y2[(size_t)b * 256 + c] = As[r * 260 + c] + hn;
        }
        __syncthreads();
        load_A32(g_H1, b0, As);
        __syncthreads();
        gate3(As, sm + OW1H, r, cg, gh1);
        gh1[0] += rnn1_bhh[c]; gh1[1] += rnn1_bhh[256 + c]; gh1[2] += rnn1_bhh[512 + c];
        __syncthreads();
        if (t + 1 < TSTEPS)
            phase_X(t + 1, attn_bhh, proj1_b, b0, c0, r, cg, c, sm);
        gridbar(lgen);
    }
    // final proj2 (t = TSTEPS-1)
    load_A32(g_Y2, b0, As);
    __syncthreads();
    {
        const int j = tid & 7, c0p = cj * 5;
        if (j < 5) {
            const ulonglong2* a8 = (const ulonglong2*)(As + r * 260);
            const ulonglong2* w8 = (const ulonglong2*)(sm + OP2 + j * 260);
            ull acc = 0;
#pragma unroll 8
            for (int k = 0; k < 64; k++) {
                ulonglong2 a = a8[k], w = w8[k];
                acc = ffma2(a.x, w.x, acc); acc = ffma2(a.y, w.y, acc);
            }
            out_mel[(size_t)(b0 + r) * 80000 + (size_t)(TSTEPS - 1) * 160 + c0p + j] =
                unpack_sum(acc) + proj2_b[c0p + j];
        }
    }
}

extern "C" void kernel_launch(void* const* d_in, const int* in_sizes, int n_in,
                              void* d_out, int out_size) {
    const float* dec      = (const float*)d_in[0];
    const float* enc      = (const float*)d_in[1];
    const float* pre_w1   = (const float*)d_in[2];
    const float* pre_b1   = (const float*)d_in[3];
    const float* pre_w2   = (const float*)d_in[4];
    const float* pre_b2   = (const float*)d_in[5];
    const float* attn_wih = (const float*)d_in[6];
    const float* attn_whh = (const float*)d_in[7];
    const float* attn_bih = (const float*)d_in[8];
    const float* attn_bhh = (const float*)d_in[9];
    const float* proj1_w  = (const float*)d_in[10];
    const float* proj1_b  = (const float*)d_in[11];
    const float* rnn1_wih = (const float*)d_in[12];
    const float* rnn1_whh = (const float*)d_in[13];
    const float* rnn1_bih = (const float*)d_in[14];
    const float* rnn1_bhh = (const float*)d_in[15];
    const float* rnn2_wih = (const float*)d_in[16];
    const float* rnn2_whh = (const float*)d_in[17];
    const float* rnn2_bih = (const float*)d_in[18];
    const float* rnn2_bhh = (const float*)d_in[19];
    const float* proj2_w  = (const float*)d_in[20];
    const float* proj2_b  = (const float*)d_in[21];
    float* out = (float*)d_out;

    float *x1, *x2, *gia;
    cudaGetSymbolAddress((void**)&x1, g_X1);
    cudaGetSymbolAddress((void**)&x2, g_X2);
    cudaGetSymbolAddress((void**)&gia, g_GIA);

    const int SMEM = SMEMF * 4;
    cudaFuncSetAttribute(decoder_loop, cudaFuncAttributeMaxDynamicSharedMemorySize, SMEM);

    transpose_enc_k<<<dim3(128, 8, 8), 256>>>(enc);
    gemm_k<true, true><<<dim3(1000, 4), 256>>>(dec, pre_w1, pre_b1, x1, 80, 256, 80);
    gemm_k<true, true><<<dim3(1000, 2), 256>>>(x1, pre_w2, pre_b2, x2, 256, 128, 256);
    gemm_k<false, true><<<dim3(1000, 12), 256>>>(x2, attn_wih, attn_bih, gia, 128, 768, 128);
    gemm_k<false, false><<<dim3(512, 4), 256>>>(enc, proj1_w, nullptr, x1, 256, 256, 512);
    decoder_loop<<<128, 256, SMEM>>>(attn_bhh, proj1_b,
                                     rnn1_bih, rnn1_bhh, rnn2_bih, rnn2_bhh,
                                     attn_whh, proj1_w,
                                     rnn1_wih, rnn1_whh, rnn2_wih, rnn2_whh,
                                     proj2_w, proj2_b, out);
    transpose_aln_k<<<dim3(128, 8, 16), 256>>>(out + 10240000);
}

// round 14
// speedup vs baseline: 2.2598x; 1.1629x over previous
#include <cuda_runtime.h>
#include <cstdint>
#include <cstddef>

#define TSTEPS 500
#define BATCH  128

// smem float offsets
#define OWA  0
#define OW1I 6240
#define OW1H 12480
#define OW2I 18720
#define OW2H 24960
#define OWR  31200
#define OST  33280
#define OT1  41600
#define SMEMF 49920   /* 199,680 bytes */

__device__ float g_X1[64000 * 256];   // prenet hidden, then encW
__device__ float g_X2[64000 * 128];
__device__ float g_GIA[64000 * 768];
__device__ float g_encT[128 * 256 * 256];
__device__ float g_ALN[64000 * 256];
__device__ float g_Y2ALL[64000 * 256];
__device__ float g_HA[2][128 * 256];
__device__ float g_H1[128 * 256];
__device__ float g_H2[128 * 256];
__device__ float g_CTX[128 * 256];
__device__ float g_DEC[128 * 256];
__device__ float g_Y1[128 * 256];
__device__ unsigned g_flag[128 * 32];
__device__ unsigned g_ggen[4 * 32];

typedef unsigned long long ull;

__device__ __forceinline__ ull ffma2(ull a, ull b, ull c) {
    ull d;
    asm("fma.rn.f32x2 %0, %1, %2, %3;" : "=l"(d) : "l"(a), "l"(b), "l"(c));
    return d;
}
__device__ __forceinline__ float unpack_sum(ull v) {
    float2 f = *(float2*)&v;
    return f.x + f.y;
}

// C[M,N] = act(A@W^T + b); guards handle N not multiple of 64 (W rows >= N zero).
template <bool RELU, bool HASB>
__global__ __launch_bounds__(256) void gemm_k(const float* __restrict__ A,
                                              const float* __restrict__ W,
                                              const float* __restrict__ bias,
                                              float* __restrict__ C, int K, int N, int ldw) {
    __shared__ float As[16 * 68];
    __shared__ float Ws[16 * 68];
    const int m0 = blockIdx.x * 64, n0 = blockIdx.y * 64;
    const int tid = threadIdx.x, tx = tid & 15, ty = tid >> 4;
    float acc[4][4] = {};
    for (int k0 = 0; k0 < K; k0 += 16) {
        int idx = tid;
#pragma unroll
        for (int it = 0; it < 4; it++) {
            int m = idx >> 4, k = idx & 15;
            As[k * 68 + m] = A[(size_t)(m0 + m) * K + k0 + k];
            int wr = n0 + m;
            Ws[k * 68 + m] = (wr < N) ? W[(size_t)wr * ldw + k0 + k] : 0.f;
            idx += 256;
        }
        __syncthreads();
#pragma unroll
        for (int k = 0; k < 16; k++) {
            float4 a = *(const float4*)&As[k * 68 + ty * 4];
            float4 w = *(const float4*)&Ws[k * 68 + tx * 4];
            acc[0][0] += a.x * w.x; acc[0][1] += a.x * w.y; acc[0][2] += a.x * w.z; acc[0][3] += a.x * w.w;
            acc[1][0] += a.y * w.x; acc[1][1] += a.y * w.y; acc[1][2] += a.y * w.z; acc[1][3] += a.y * w.w;
            acc[2][0] += a.z * w.x; acc[2][1] += a.z * w.y; acc[2][2] += a.z * w.z; acc[2][3] += a.z * w.w;
            acc[3][0] += a.w * w.x; acc[3][1] += a.w * w.y; acc[3][2] += a.w * w.z; acc[3][3] += a.w * w.w;
        }
        __syncthreads();
    }
#pragma unroll
    for (int i = 0; i < 4; i++) {
        int m = m0 + ty * 4 + i;
#pragma unroll
        for (int j = 0; j < 4; j++) {
            int col = n0 + tx * 4 + j;
            if (col < N) {
                float v = acc[i][j] + (HASB ? bias[col] : 0.f);
                if (RELU) v = fmaxf(v, 0.f);
                C[(size_t)m * N + col] = v;
            }
        }
    }
}

__global__ void transpose_enc_k(const float* __restrict__ enc) {
    __shared__ float tile[32][33];
    const int b = blockIdx.x, l0 = blockIdx.y * 32, d0 = blockIdx.z * 32;
    const int j = threadIdx.x & 31, i0 = threadIdx.x >> 5;
    const float* base = enc + (size_t)b * 65536;
#pragma unroll
    for (int ii = 0; ii < 32; ii += 8)
        tile[i0 + ii][j] = base[(size_t)(l0 + i0 + ii) * 256 + d0 + j];
    __syncthreads();
    float* ob = g_encT + (size_t)b * 65536;
#pragma unroll
    for (int ii = 0; ii < 32; ii += 8)
        ob[(size_t)(d0 + i0 + ii) * 256 + l0 + j] = tile[j][i0 + ii];
}

__global__ void transpose_aln_k(float* __restrict__ out) {
    __shared__ float tile[32][33];
    const int b = blockIdx.x, l0 = blockIdx.y * 32, t0 = blockIdx.z * 32;
    const int j = threadIdx.x & 31, i0 = threadIdx.x >> 5;
#pragma unroll
    for (int ii = 0; ii < 32; ii += 8) {
        int t = t0 + i0 + ii;
        if (t < TSTEPS) tile[i0 + ii][j] = g_ALN[((size_t)t * BATCH + b) * 256 + l0 + j];
    }
    __syncthreads();
#pragma unroll
    for (int ii = 0; ii < 32; ii += 8) {
        int t = t0 + j, l = l0 + i0 + ii;
        if (t < TSTEPS) out[((size_t)b * 256 + l) * TSTEPS + t] = tile[j][i0 + ii];
    }
}

__device__ __forceinline__ float sigm(float x) { return 1.f / (1.f + expf(-x)); }

// group-local barrier: 32 CTAs per group, no atomics, no global coupling
__device__ __forceinline__ void groupbar(unsigned& lgen, int grp, int cj) {
    __syncthreads();
    lgen++;
    if (cj == 0) {
        if (threadIdx.x >= 1 && threadIdx.x < 32) {
            const unsigned* f = &g_flag[(grp * 32 + threadIdx.x) * 32];
            unsigned v;
            do {
                asm volatile("ld.acquire.gpu.global.u32 %0, [%1];" : "=r"(v) : "l"(f) : "memory");
            } while ((int)(v - lgen) < 0);
        }
        __syncthreads();
        if (threadIdx.x == 0)
            asm volatile("st.release.gpu.global.u32 [%0], %1;"
                         :: "l"(&g_ggen[grp * 32]), "r"(lgen) : "memory");
    } else {
        if (threadIdx.x == 0) {
            asm volatile("st.release.gpu.global.u32 [%0], %1;"
                         :: "l"(&g_flag[blockIdx.x * 32]), "r"(lgen) : "memory");
            unsigned v;
            do {
                asm volatile("ld.acquire.gpu.global.u32 %0, [%1];"
                             : "=r"(v) : "l"(&g_ggen[grp * 32]) : "memory");
            } while ((int)(v - lgen) < 0);
        }
        __syncthreads();
    }
}

__device__ __forceinline__ void load_A32(const float* __restrict__ src, int b0, float* As) {
    for (int idx = threadIdx.x; idx < 32 * 64; idx += 256) {
        int r = idx >> 6, q = idx & 63;
        *(float4*)(As + r * 260 + q * 4) = *(const float4*)(src + (size_t)(b0 + r) * 256 + q * 4);
    }
}

__device__ __forceinline__ void load_A32sum(const float* __restrict__ sa,
                                            const float* __restrict__ sb, int b0, float* As) {
    for (int idx = threadIdx.x; idx < 32 * 64; idx += 256) {
        int r = idx >> 6, q = idx & 63;
        float4 a = *(const float4*)(sa + (size_t)(b0 + r) * 256 + q * 4);
        float4 b = *(const float4*)(sb + (size_t)(b0 + r) * 256 + q * 4);
        a.x += b.x; a.y += b.y; a.z += b.z; a.w += b.w;
        *(float4*)(As + r * 260 + q * 4) = a;
    }
}

__device__ __forceinline__ void preload_W24(const float* __restrict__ w, int c0, float* Wd) {
    for (int idx = threadIdx.x; idx < 24 * 64; idx += 256) {
        int row = idx >> 6, q = idx & 63;
        int g = row >> 3, i = row & 7;
        *(float4*)(Wd + row * 260 + q * 4) =
            *(const float4*)(w + (size_t)(g * 256 + c0 + i) * 256 + q * 4);
    }
}

__device__ __forceinline__ void gate3(const float* As, const float* Ws, int r, int cg, float out[3]) {
    const ulonglong2* a8 = (const ulonglong2*)(As + r * 260);
    const ulonglong2* w0 = (const ulonglong2*)(Ws + cg * 260);
    const ulonglong2* w1 = (const ulonglong2*)(Ws + (8 + cg) * 260);
    const ulonglong2* w2 = (const ulonglong2*)(Ws + (16 + cg) * 260);
    ull acc0 = 0, acc1 = 0, acc2 = 0;
#pragma unroll 8
    for (int k = 0; k < 64; k++) {
        ulonglong2 a = a8[k];
        ulonglong2 b0 = w0[k], b1 = w1[k], b2 = w2[k];
        acc0 = ffma2(a.x, b0.x, acc0); acc0 = ffma2(a.y, b0.y, acc0);
        acc1 = ffma2(a.x, b1.x, acc1); acc1 = ffma2(a.y, b1.y, acc1);
        acc2 = ffma2(a.x, b2.x, acc2); acc2 = ffma2(a.y, b2.y, acc2);
    }
    out[0] = unpack_sum(acc0);
    out[1] = unpack_sum(acc1);
    out[2] = unpack_sum(acc2);
}

// X(ta): attention(ta) for row b + attnGRU -> hA(ta+1) + hWr(ta)
__device__ void phase_X(int ta, const float* __restrict__ attn_bhh,
                        const float* __restrict__ proj1_b,
                        int b0, int b, int r, int cg, int c, float* sm) {
    const int tid = threadIdx.x;
    const int p = ta & 1;
    float* As = sm + OST;
    float* q = sm + OST;
    float* sc = sm + OST + 256;
    float* sp = sm + OST + 512;   // 4*256 partials
    __shared__ float red[8];
    __shared__ float redv[2];
    __syncthreads();
    q[tid] = g_HA[p][(size_t)b * 256 + tid];
    __syncthreads();
    // score partials: thread = (l4 group, d quarter), float4 over l
    {
        const int l4 = (tid & 63) * 4, dq = tid >> 6;
        const float* ep = g_encT + (size_t)b * 65536 + (size_t)(dq * 64) * 256 + l4;
        const float* qq = q + dq * 64;
        float4 s4 = {0.f, 0.f, 0.f, 0.f};
#pragma unroll 8
        for (int d = 0; d < 64; d++) {
            float4 v = *(const float4*)(ep + d * 256);
            float qv = qq[d];
            s4.x += qv * v.x; s4.y += qv * v.y; s4.z += qv * v.z; s4.w += qv * v.w;
        }
        *(float4*)(sp + dq * 256 + l4) = s4;
    }
    __syncthreads();
    float s = (sp[tid] + sp[256 + tid]) + (sp[512 + tid] + sp[768 + tid]);
    float m = s;
#pragma unroll
    for (int off = 16; off > 0; off >>= 1) m = fmaxf(m, __shfl_xor_sync(~0u, m, off));
    const int w = tid >> 5;
    if ((tid & 31) == 0) red[w] = m;
    __syncthreads();
    if (tid < 8) {
        float x = red[tid];
#pragma unroll
        for (int off = 4; off > 0; off >>= 1) x = fmaxf(x, __shfl_xor_sync(0xffu, x, off));
        if (tid == 0) redv[0] = x;
    }
    __syncthreads();
    float e = expf(s - redv[0]);
    float su = e;
#pragma unroll
    for (int off = 16; off > 0; off >>= 1) su += __shfl_xor_sync(~0u, su, off);
    if ((tid & 31) == 0) red[w] = su;
    __syncthreads();
    if (tid < 8) {
        float x = red[tid];
#pragma unroll
        for (int off = 4; off > 0; off >>= 1) x += __shfl_xor_sync(0xffu, x, off);
        if (tid == 0) redv[1] = x;
    }
    __syncthreads();
    float wgt = e / redv[1];
    sc[tid] = wgt;
    g_ALN[((size_t)ta * BATCH + b) * 256 + tid] = wgt;
    __syncthreads();
    // ctx partials: thread = (d4 group, l quarter), float4 over d
    {
        const int d4 = (tid & 63) * 4, lq = tid >> 6;
        const float* ew = g_X1 + (size_t)b * 65536 + (size_t)(lq * 64) * 256 + d4;
        const float* ss = sc + lq * 64;
        float4 c4 = {0.f, 0.f, 0.f, 0.f};
#pragma unroll 8
        for (int l = 0; l < 64; l++) {
            float4 v = *(const float4*)(ew + l * 256);
            float sv = ss[l];
            c4.x += sv * v.x; c4.y += sv * v.y; c4.z += sv * v.z; c4.w += sv * v.w;
        }
        *(float4*)(sp + lq * 256 + d4) = c4;
    }
    __syncthreads();
    g_CTX[(size_t)b * 256 + tid] = (sp[tid] + sp[256 + tid]) + (sp[512 + tid] + sp[768 + tid]);
    __syncthreads();
    load_A32(g_HA[p], b0, As);
    __syncthreads();
    if (ta + 1 < TSTEPS) {   // attnGRU -> hA(ta+1)
        float acc[3];
        gate3(As, sm + OWA, r, cg, acc);
        const int bm = b0 + r;
        const float* gb = g_GIA + ((size_t)bm * TSTEPS + ta + 1) * 768;
        float rr = sigm(gb[c] + acc[0] + attn_bhh[c]);
        float zz = sigm(gb[256 + c] + acc[1] + attn_bhh[256 + c]);
        float nn = tanhf(gb[512 + c] + rr * (acc[2] + attn_bhh[512 + c]));
        float hp = As[r * 260 + c];
        g_HA[p ^ 1][(size_t)bm * 256 + c] = (1.f - zz) * nn + zz * hp;
    }
    {   // hWr(ta)
        const ulonglong2* a8 = (const ulonglong2*)(As + r * 260);
        const ulonglong2* w8 = (const ulonglong2*)(sm + OWR + cg * 260);
        ull acc = 0;
#pragma unroll 8
        for (int k = 0; k < 64; k++) {
            ulonglong2 a = a8[k], w2 = w8[k];
            acc = ffma2(a.x, w2.x, acc); acc = ffma2(a.y, w2.y, acc);
        }
        g_DEC[(size_t)(b0 + r) * 256 + c] = unpack_sum(acc) + proj1_b[c];
    }
}

__global__ __launch_bounds__(256) void decoder_loop(
    const float* __restrict__ attn_bhh,
    const float* __restrict__ proj1_b,
    const float* __restrict__ rnn1_bih, const float* __restrict__ rnn1_bhh,
    const float* __restrict__ rnn2_bih, const float* __restrict__ rnn2_bhh,
    const float* __restrict__ attn_whh,
    const float* __restrict__ proj1_w,
    const float* __restrict__ rnn1_wih, const float* __restrict__ rnn1_whh,
    const float* __restrict__ rnn2_wih, const float* __restrict__ rnn2_whh) {
    extern __shared__ float sm[];
    const int tid = threadIdx.x;
    const int grp = blockIdx.x >> 5, cj = blockIdx.x & 31;
    const int b0 = grp * 32, c0 = cj * 8;
    const int b = b0 + cj;                 // this CTA's attention row
    const int r = tid >> 3, cg = tid & 7, c = c0 + cg;
    float* T0 = sm + OST;
    float* T1 = sm + OT1;
    unsigned lgen;
    asm volatile("ld.acquire.gpu.global.u32 %0, [%1];" : "=r"(lgen) : "l"(&g_ggen[grp * 32]) : "memory");

    preload_W24(attn_whh, c0, sm + OWA);
    preload_W24(rnn1_wih, c0, sm + OW1I);
    preload_W24(rnn1_whh, c0, sm + OW1H);
    preload_W24(rnn2_wih, c0, sm + OW2I);
    preload_W24(rnn2_whh, c0, sm + OW2H);
    for (int idx = tid; idx < 8 * 64; idx += 256) {
        int row = idx >> 6, qq = idx & 63;
        *(float4*)(sm + OWR + row * 260 + qq * 4) =
            *(const float4*)(proj1_w + (size_t)(c0 + row) * 512 + 256 + qq * 4);
    }
    // prologue
    {
        int i = blockIdx.x * 256 + tid;
        g_H1[i] = 0.f;
        g_H2[i] = 0.f;
        const int bm = b0 + r;
        const float* gb = g_GIA + ((size_t)bm * TSTEPS) * 768;
        float rr = sigm(gb[c] + attn_bhh[c]);
        float zz = sigm(gb[256 + c] + attn_bhh[256 + c]);
        float nn = tanhf(gb[512 + c] + rr * attn_bhh[512 + c]);
        g_HA[0][(size_t)bm * 256 + c] = (1.f - zz) * nn;
    }
    float gh1[3] = { rnn1_bhh[c], rnn1_bhh[256 + c], rnn1_bhh[512 + c] };
    float gh2[3];
    groupbar(lgen, grp, cj);
    phase_X(0, attn_bhh, proj1_b, b0, b, r, cg, c, sm);
    groupbar(lgen, grp, cj);

    for (int t = 0; t < TSTEPS; t++) {
        // ===== A(t): rnn1 + gh2(t) =====
        load_A32sum(g_CTX, g_DEC, b0, T0);
        load_A32(g_H2, b0, T1);
        __syncthreads();
        {
            float acc[3];
            gate3(T0, sm + OW1I, r, cg, acc);
            const int bm = b0 + r;
            float rr = sigm(acc[0] + rnn1_bih[c] + gh1[0]);
            float zz = sigm(acc[1] + rnn1_bih[256 + c] + gh1[1]);
            float nn = tanhf(acc[2] + rnn1_bih[512 + c] + rr * gh1[2]);
            float hp = g_H1[(size_t)bm * 256 + c];
            float hn = (1.f - zz) * nn + zz * hp;
            g_H1[(size_t)bm * 256 + c] = hn;
            g_Y1[(size_t)bm * 256 + c] = T0[r * 260 + c] + hn;
        }
        gate3(T1, sm + OW2H, r, cg, gh2);
        gh2[0] += rnn2_bhh[c]; gh2[1] += rnn2_bhh[256 + c]; gh2[2] += rnn2_bhh[512 + c];
        groupbar(lgen, grp, cj);
        // ===== B(t): rnn2 + gh1(t+1) + X(t+1) =====
        load_A32(g_Y1, b0, T0);
        load_A32(g_H1, b0, T1);
        __syncthreads();
        {
            float acc[3];
            gate3(T0, sm + OW2I, r, cg, acc);
            const int bm = b0 + r;
            float rr = sigm(acc[0] + rnn2_bih[c] + gh2[0]);
            float zz = sigm(acc[1] + rnn2_bih[256 + c] + gh2[1]);
            float nn = tanhf(acc[2] + rnn2_bih[512 + c] + rr * gh2[2]);
            float hp = g_H2[(size_t)bm * 256 + c];
            float hn = (1.f - zz) * nn + zz * hp;
            g_H2[(size_t)bm * 256 + c] = hn;
            g_Y2ALL[((size_t)bm * TSTEPS + t) * 256 + c] = T0[r * 260 + c] + hn;
        }
        gate3(T1, sm + OW1H, r, cg, gh1);
        gh1[0] += rnn1_bhh[c]; gh1[1] += rnn1_bhh[256 + c]; gh1[2] += rnn1_bhh[512 + c];
        if (t + 1 < TSTEPS)
            phase_X(t + 1, attn_bhh, proj1_b, b0, b, r, cg, c, sm);
        groupbar(lgen, grp, cj);
    }
}

extern "C" void kernel_launch(void* const* d_in, const int* in_sizes, int n_in,
                              void* d_out, int out_size) {
    const float* dec      = (const float*)d_in[0];
    const float* enc      = (const float*)d_in[1];
    const float* pre_w1   = (const float*)d_in[2];
    const float* pre_b1   = (const float*)d_in[3];
    const float* pre_w2   = (const float*)d_in[4];
    const float* pre_b2   = (const float*)d_in[5];
    const float* attn_wih = (const float*)d_in[6];
    const float* attn_whh = (const float*)d_in[7];
    const float* attn_bih = (const float*)d_in[8];
    const float* attn_bhh = (const float*)d_in[9];
    const float* proj1_w  = (const float*)d_in[10];
    const float* proj1_b  = (const float*)d_in[11];
    const float* rnn1_wih = (const float*)d_in[12];
    const float* rnn1_whh = (const float*)d_in[13];
    const float* rnn1_bih = (const float*)d_in[14];
    const float* rnn1_bhh = (const float*)d_in[15];
    const float* rnn2_wih = (const float*)d_in[16];
    const float* rnn2_whh = (const float*)d_in[17];
    const float* rnn2_bih = (const float*)d_in[18];
    const float* rnn2_bhh = (const float*)d_in[19];
    const float* proj2_w  = (const float*)d_in[20];
    const float* proj2_b  = (const float*)d_in[21];
    float* out = (float*)d_out;

    float *x1, *x2, *gia, *y2all;
    cudaGetSymbolAddress((void**)&x1, g_X1);
    cudaGetSymbolAddress((void**)&x2, g_X2);
    cudaGetSymbolAddress((void**)&gia, g_GIA);
    cudaGetSymbolAddress((void**)&y2all, g_Y2ALL);

    const int SMEM = SMEMF * 4;
    cudaFuncSetAttribute(decoder_loop, cudaFuncAttributeMaxDynamicSharedMemorySize, SMEM);

    transpose_enc_k<<<dim3(128, 8, 8), 256>>>(enc);
    gemm_k<true, true><<<dim3(1000, 4), 256>>>(dec, pre_w1, pre_b1, x1, 80, 256, 80);
    gemm_k<true, true><<<dim3(1000, 2), 256>>>(x1, pre_w2, pre_b2, x2, 256, 128, 256);
    gemm_k<false, true><<<dim3(1000, 12), 256>>>(x2, attn_wih, attn_bih, gia, 128, 768, 128);
    gemm_k<false, false><<<dim3(512, 4), 256>>>(enc, proj1_w, nullptr, x1, 256, 256, 512);
    decoder_loop<<<128, 256, SMEM>>>(attn_bhh, proj1_b,
                                     rnn1_bih, rnn1_bhh, rnn2_bih, rnn2_bhh,
                                     attn_whh, proj1_w,
                                     rnn1_wih, rnn1_whh, rnn2_wih, rnn2_whh);
    // proj2 batched: rows m=(b*500+t); C index m*160+j == out[b*80000+t*160+j]
    gemm_k<false, true><<<dim3(1000, 3), 256>>>(y2all, proj2_w, proj2_b, out, 256, 160, 256);
    transpose_aln_k<<<dim3(128, 8, 16), 256>>>(out + 10240000);
}